// round 5
// baseline (speedup 1.0000x reference)
#include <cuda_runtime.h>
#include <cuda_bf16.h>
#include <cstdint>
#include <math.h>

#define Bsz 4
#define Nn 4096
#define DIMc 256
#define Hh 8
#define DHd 64
#define Pp 2
#define INNERc 512
#define MQ (Bsz*Nn)      /* 16384 */
#define MKV (2*Bsz*Nn)   /* 32768 */

typedef __nv_bfloat16 bf16;

// ---------------- scratch (device globals) ----------------
__device__ bf16  g_qlnh[MQ * INNERc];
__device__ bf16  g_qlnl[MQ * INNERc];
__device__ float g_q   [MQ * INNERc];
__device__ bf16  g_nh  [MKV * DIMc];       // LN(kv) normalized, hi
__device__ bf16  g_nl  [MKV * DIMc];       // LN(kv) normalized, lo
__device__ float g_kv  [MKV * 2 * INNERc]; // fused k|v output [row, 1024]
__device__ float g_off [MQ * 16];
__device__ bf16  g_aoh [MQ * INNERc];
__device__ bf16  g_aol [MQ * INNERc];
__device__ bf16  g_wqTh[INNERc * INNERc];
__device__ bf16  g_wqTl[INNERc * INNERc];
__device__ bf16  g_wkvTh[2 * INNERc * DIMc];  // [1024, 256]
__device__ bf16  g_wkvTl[2 * INNERc * DIMc];
__device__ bf16  g_wouth[DIMc * INNERc];
__device__ bf16  g_woutl[DIMc * INNERc];
__device__ float g_biasq [INNERc];
__device__ float g_biaskv[2 * INNERc];

// ================= helpers =================
__device__ __forceinline__ uint32_t smem_u32(const void* p){
    uint32_t a;
    asm("{ .reg .u64 t; cvta.to.shared.u64 t, %1; cvt.u32.u64 %0, t; }" : "=r"(a) : "l"(p));
    return a;
}
__device__ __forceinline__ void bsplit(float v, bf16& h, bf16& l){
    h = __float2bfloat16(v);
    l = __float2bfloat16(v - __bfloat162float(h));
}
__device__ __forceinline__ void mma_bf16(float d[4], const uint32_t a[4], const uint32_t b[2]){
    asm volatile("mma.sync.aligned.m16n8k16.row.col.f32.bf16.bf16.f32 "
        "{%0,%1,%2,%3}, {%4,%5,%6,%7}, {%8,%9}, {%0,%1,%2,%3};"
        : "+f"(d[0]),"+f"(d[1]),"+f"(d[2]),"+f"(d[3])
        : "r"(a[0]),"r"(a[1]),"r"(a[2]),"r"(a[3]),"r"(b[0]),"r"(b[1]));
}
__device__ __forceinline__ void ldsm4(uint32_t r[4], uint32_t addr){
    asm volatile("ldmatrix.sync.aligned.m8n8.x4.shared.b16 {%0,%1,%2,%3}, [%4];"
        : "=r"(r[0]),"=r"(r[1]),"=r"(r[2]),"=r"(r[3]) : "r"(addr));
}
__device__ __forceinline__ void cp16(uint32_t dst, const void* src){
    asm volatile("cp.async.cg.shared.global [%0], [%1], 16;" :: "r"(dst), "l"(src));
}

// ================= bf16x3 tensor-core GEMM =================
// C[M,Ntot] = (Ah+Al)[M,K] @ (Bh+Bl)[Ntot,K]^T (+bias), x3 terms.
// 256 thr, tile 128x128, K-chunk 32, 4-stage cp.async (depth 3), 1 sync/chunk.
#define TILE_B 10240
#define STAGE_B 40960
#define GEMM_SMEM (4*STAGE_B)

template<int HAS_BIAS>
__global__ void __launch_bounds__(256, 1)
bf16x3_gemm(const bf16* __restrict__ Ah, const bf16* __restrict__ Al,
            const bf16* __restrict__ Bh, const bf16* __restrict__ Bl,
            const float* __restrict__ bias, float* __restrict__ C,
            int Ntot, int K)
{
    extern __shared__ char smem[];
    const uint32_t sb = smem_u32(smem);
    const int tid = threadIdx.x, lane = tid & 31, wid = tid >> 5;
    const int wm = wid >> 2, wn = wid & 3;         // 2x4 warp grid, 64x32 per warp
    const int bm = blockIdx.y * 128, bn = blockIdx.x * 128;
    const int NC = K >> 5;

    const int lr  = tid >> 2;       // 0..63
    const int lcc = tid & 3;        // 16B chunk within 32-k row segment

    auto load_stage = [&](int buf, int kc){
        uint32_t sbase = sb + buf * STAGE_B + lr * 80 + lcc * 16;
        size_t ao = (size_t)(bm + lr) * K + kc + lcc * 8;
        size_t bo = (size_t)(bn + lr) * K + kc + lcc * 8;
        size_t row64 = (size_t)64 * K;
        cp16(sbase,                    Ah + ao);
        cp16(sbase + 64*80,            Ah + ao + row64);
        cp16(sbase + TILE_B,           Al + ao);
        cp16(sbase + TILE_B + 64*80,   Al + ao + row64);
        cp16(sbase + 2*TILE_B,         Bh + bo);
        cp16(sbase + 2*TILE_B + 64*80, Bh + bo + row64);
        cp16(sbase + 3*TILE_B,         Bl + bo);
        cp16(sbase + 3*TILE_B + 64*80, Bl + bo + row64);
        asm volatile("cp.async.commit_group;" ::: "memory");
    };

    float acc[4][4][4] = {};
    const uint32_t arow = (uint32_t)(lane & 15) * 80 + (uint32_t)(lane >> 4) * 16;

    auto compute = [&](int buf){
        uint32_t base = sb + buf * STAGE_B;
        #pragma unroll
        for (int ks = 0; ks < 2; ks++){
            uint32_t ah[4][4], al_[4][4], bh[4][2], bl[4][2];
            #pragma unroll
            for (int i = 0; i < 4; i++){
                uint32_t a = base + (uint32_t)(wm*64 + i*16) * 80 + arow + ks*32;
                ldsm4(ah[i],  a);
                ldsm4(al_[i], a + TILE_B);
            }
            #pragma unroll
            for (int jp = 0; jp < 2; jp++){
                uint32_t a = base + 2*TILE_B + (uint32_t)(wn*32 + jp*16) * 80 + arow + ks*32;
                uint32_t r4[4];
                ldsm4(r4, a);
                bh[jp*2][0]=r4[0]; bh[jp*2+1][0]=r4[1]; bh[jp*2][1]=r4[2]; bh[jp*2+1][1]=r4[3];
                ldsm4(r4, a + TILE_B);
                bl[jp*2][0]=r4[0]; bl[jp*2+1][0]=r4[1]; bl[jp*2][1]=r4[2]; bl[jp*2+1][1]=r4[3];
            }
            #pragma unroll
            for (int i = 0; i < 4; i++)
                #pragma unroll
                for (int j = 0; j < 4; j++){
                    mma_bf16(acc[i][j], ah[i],  bh[j]);
                    mma_bf16(acc[i][j], ah[i],  bl[j]);
                    mma_bf16(acc[i][j], al_[i], bh[j]);
                }
        }
    };

    load_stage(0, 0);
    load_stage(1, 32);
    load_stage(2, 64);

    for (int c = 0; c < NC; c++){
        if (c <= NC - 3)      asm volatile("cp.async.wait_group 2;" ::: "memory");
        else if (c == NC - 2) asm volatile("cp.async.wait_group 1;" ::: "memory");
        else                  asm volatile("cp.async.wait_group 0;" ::: "memory");
        __syncthreads();
        if (c + 3 < NC) load_stage((c + 3) & 3, (c + 3) * 32);
        compute(c & 3);
    }

    #pragma unroll
    for (int i = 0; i < 4; i++){
        int r0 = bm + wm*64 + i*16 + (lane >> 2);
        #pragma unroll
        for (int j = 0; j < 4; j++){
            int c0 = bn + wn*32 + j*8 + (lane & 3)*2;
            float b0 = 0.f, b1 = 0.f;
            if (HAS_BIAS){ b0 = bias[c0]; b1 = bias[c0+1]; }
            *(float2*)(C + (size_t)r0 * Ntot + c0)     = make_float2(acc[i][j][0]+b0, acc[i][j][1]+b1);
            *(float2*)(C + (size_t)(r0+8) * Ntot + c0) = make_float2(acc[i][j][2]+b0, acc[i][j][3]+b1);
        }
    }
}

// ========= transpose + gamma-fold + split: out[n,k] = split(g[k]*W[k,n]) =========
__global__ void transpose_split_scale(const float* __restrict__ in, const float* __restrict__ g,
                                      bf16* __restrict__ oh, bf16* __restrict__ ol,
                                      int R, int C){
    __shared__ float tile[32][33];
    int c0 = blockIdx.x * 32, r0 = blockIdx.y * 32;
    int tx = threadIdx.x, ty = threadIdx.y;
    #pragma unroll
    for (int i = 0; i < 32; i += 8){
        int r = r0 + ty + i;
        tile[ty + i][tx] = in[(size_t)r * C + c0 + tx] * g[r];
    }
    __syncthreads();
    #pragma unroll
    for (int i = 0; i < 32; i += 8){
        float v = tile[tx][ty + i];
        bf16 h, l; bsplit(v, h, l);
        size_t o = (size_t)(c0 + ty + i) * R + r0 + tx;
        oh[o] = h; ol[o] = l;
    }
}

// ========= bias fold: out[n] = (base?base[n]:0) + sum_k beta[k]*W[k,n] =========
__global__ void fold_bias(const float* __restrict__ W, const float* __restrict__ beta,
                          const float* __restrict__ base, float* __restrict__ out,
                          int K, int N){
    int n = blockIdx.x * blockDim.x + threadIdx.x;
    if (n >= N) return;
    float s = base ? base[n] : 0.f;
    for (int k = 0; k < K; k++) s += beta[k] * W[(size_t)k * N + n];
    out[n] = s;
}

// ================= elementwise split (Wout) =================
__global__ void split_kernel(const float* __restrict__ in,
                             bf16* __restrict__ oh, bf16* __restrict__ ol, int n){
    int i = blockIdx.x * blockDim.x + threadIdx.x;
    if (i >= n) return;
    bf16 h, l; bsplit(in[i], h, l);
    oh[i] = h; ol[i] = l;
}

// ================= block reduce =================
__device__ __forceinline__ float2 blockReduce2(float a, float b) {
    __shared__ float2 sbuf[8];
    #pragma unroll
    for (int o = 16; o > 0; o >>= 1) {
        a += __shfl_xor_sync(0xffffffffu, a, o);
        b += __shfl_xor_sync(0xffffffffu, b, o);
    }
    int w = threadIdx.x >> 5;
    if ((threadIdx.x & 31) == 0) sbuf[w] = make_float2(a, b);
    __syncthreads();
    if (w == 0) {
        int nw = blockDim.x >> 5;
        float2 r = (threadIdx.x < nw) ? sbuf[threadIdx.x] : make_float2(0.f, 0.f);
        #pragma unroll
        for (int o = 4; o > 0; o >>= 1) {
            r.x += __shfl_xor_sync(0xffffffffu, r.x, o);
            r.y += __shfl_xor_sync(0xffffffffu, r.y, o);
        }
        if (threadIdx.x == 0) sbuf[0] = r;
    }
    __syncthreads();
    return sbuf[0];
}

// ============ LN over concat (512) — emits PLAIN normalized planes ============
__global__ void lnq_kernel(const float* __restrict__ x, const float* __restrict__ px,
                           bf16* __restrict__ oh, bf16* __restrict__ ol) {
    int row = blockIdx.x;
    int t = threadIdx.x;
    float v0 = x [row * DIMc + t];
    float v1 = px[row * DIMc + t];
    float2 r = blockReduce2(v0 + v1, v0 * v0 + v1 * v1);
    float mean = r.x * (1.0f / 512.0f);
    float var  = r.y * (1.0f / 512.0f) - mean * mean;
    float rstd = rsqrtf(var + 1e-5f);
    bf16 h, l;
    bsplit((v0 - mean) * rstd, h, l); oh[row * INNERc + t] = h;       ol[row * INNERc + t] = l;
    bsplit((v1 - mean) * rstd, h, l); oh[row * INNERc + 256 + t] = h; ol[row * INNERc + 256 + t] = l;
}

// ============ LN over kv (256) — single normalized plane pair ============
__global__ void lnkv_kernel(const float* __restrict__ x, const float* __restrict__ px,
                            bf16* __restrict__ nh, bf16* __restrict__ nl) {
    int row = blockIdx.x;
    int t = threadIdx.x;
    const float* src = (row < Bsz * Nn) ? x : px;
    int r2 = (row < Bsz * Nn) ? row : row - Bsz * Nn;
    float v = src[r2 * DIMc + t];
    float2 r = blockReduce2(v, v * v);
    float mean = r.x * (1.0f / 256.0f);
    float var  = r.y * (1.0f / 256.0f) - mean * mean;
    float rstd = rsqrtf(var + 1e-5f);
    bf16 h, l;
    bsplit((v - mean) * rstd, h, l);
    nh[row * DIMc + t] = h; nl[row * DIMc + t] = l;
}

// ============ offsets projection (fp32) + fused transposed output ============
__global__ void off_kernel(const float* __restrict__ q, const float* __restrict__ Woff,
                           const float* __restrict__ boff, float* __restrict__ off,
                           float* __restrict__ off_out) {
    __shared__ float w[16][INNERc];
    int tid = threadIdx.x;
    for (int i = tid; i < 16 * INNERc; i += 128) w[i >> 9][i & 511] = Woff[i];
    __syncthreads();
    int m = blockIdx.x * 128 + tid;        // b*N + n
    const float* qr = q + (size_t)m * INNERc;
    float acc[16];
    #pragma unroll
    for (int j = 0; j < 16; j++) acc[j] = boff[j];
    for (int k0 = 0; k0 < INNERc; k0 += 4){
        float4 qv = *(const float4*)(qr + k0);
        #pragma unroll
        for (int j = 0; j < 16; j++)
            acc[j] += qv.x * w[j][k0] + qv.y * w[j][k0+1] + qv.z * w[j][k0+2] + qv.w * w[j][k0+3];
    }
    int b = m >> 12, n = m & 4095;
    #pragma unroll
    for (int j = 0; j < 16; j++){
        off[(size_t)m * 16 + j] = acc[j];
        off_out[((size_t)(b * 16 + j)) * Nn + n] = acc[j];
    }
}

// ================= attention (fused KV layout [row,1024]) =================
__global__ void attn_kernel(const float* __restrict__ q, const float* __restrict__ kv,
                            const float* __restrict__ off,
                            bf16* __restrict__ aoh, bf16* __restrict__ aol) {
    int gw = (blockIdx.x * blockDim.x + threadIdx.x) >> 5;
    int lane = threadIdx.x & 31;
    if (gw >= MQ * Hh) return;
    int bn = gw / Hh;
    int h  = gw - bn * Hh;
    int b  = bn / Nn;
    int n  = bn - b * Nn;

    float o0 = off[bn * 16 + h * Pp + 0];
    float o1 = off[bn * 16 + h * Pp + 1];
    float t0 = fminf(fmaxf((float)n + o0, 0.f), (float)(2 * Nn - 1));
    float t1 = fminf(fmaxf((float)n + o1, 0.f), (float)(2 * Nn - 1));
    int j0 = (int)t0, j1 = (int)t1;
    int s0 = (j0 >= Nn) ? 1 : 0; int np0 = j0 - s0 * Nn;
    int s1 = (j1 >= Nn) ? 1 : 0; int np1 = j1 - s1 * Nn;

    const float* qb  = q + (size_t)bn * INNERc + h * DHd;
    const float* r0p = kv + ((size_t)(s0 * Bsz + b) * Nn + np0) * (2*INNERc) + h * DHd;
    const float* r1p = kv + ((size_t)(s1 * Bsz + b) * Nn + np1) * (2*INNERc) + h * DHd;

    float qa = qb[lane], qc = qb[lane + 32];
    float d0 = qa * r0p[lane] + qc * r0p[lane + 32];
    float d1 = qa * r1p[lane] + qc * r1p[lane + 32];
    #pragma unroll
    for (int o = 16; o > 0; o >>= 1) {
        d0 += __shfl_xor_sync(0xffffffffu, d0, o);
        d1 += __shfl_xor_sync(0xffffffffu, d1, o);
    }
    const float scale = 0.125f;
    d0 *= scale; d1 *= scale;
    float mx = fmaxf(d0, d1);
    float e0 = __expf(d0 - mx), e1 = __expf(d1 - mx);
    float inv = 1.0f / (e0 + e1);
    float a0 = e0 * inv, a1 = e1 * inv;

    const float* v0p = r0p + INNERc;
    const float* v1p = r1p + INNERc;
    float r0 = a0 * v0p[lane]      + a1 * v1p[lane];
    float r1 = a0 * v0p[lane + 32] + a1 * v1p[lane + 32];
    bf16 hh, ll;
    size_t o_base = (size_t)bn * INNERc + h * DHd;
    bsplit(r0, hh, ll); aoh[o_base + lane]      = hh; aol[o_base + lane]      = ll;
    bsplit(r1, hh, ll); aoh[o_base + lane + 32] = hh; aol[o_base + lane + 32] = ll;
}

// ================= launch =================
extern "C" void kernel_launch(void* const* d_in, const int* in_sizes, int n_in,
                              void* d_out, int out_size) {
    const float* x     = (const float*)d_in[0];
    const float* px    = (const float*)d_in[1];
    const float* lnqg  = (const float*)d_in[2];
    const float* lnqb  = (const float*)d_in[3];
    const float* lnkg  = (const float*)d_in[4];
    const float* lnkb  = (const float*)d_in[5];
    const float* lnvg  = (const float*)d_in[6];
    const float* lnvb  = (const float*)d_in[7];
    const float* Wq    = (const float*)d_in[8];
    const float* Wk    = (const float*)d_in[9];
    const float* bk    = (const float*)d_in[10];
    const float* Wv    = (const float*)d_in[11];
    const float* bv    = (const float*)d_in[12];
    const float* Woff  = (const float*)d_in[13];
    const float* boff  = (const float*)d_in[14];
    const float* Wout  = (const float*)d_in[15];
    const float* bout  = (const float*)d_in[16];

    bf16 *qlnh,*qlnl,*nh,*nl,*aoh,*aol;
    bf16 *wqTh,*wqTl,*wkvTh,*wkvTl,*wouth,*woutl;
    float *qb,*kvb,*off,*biasq,*biaskv;
    cudaGetSymbolAddress((void**)&qlnh, g_qlnh);
    cudaGetSymbolAddress((void**)&qlnl, g_qlnl);
    cudaGetSymbolAddress((void**)&qb,   g_q);
    cudaGetSymbolAddress((void**)&nh,   g_nh);
    cudaGetSymbolAddress((void**)&nl,   g_nl);
    cudaGetSymbolAddress((void**)&kvb,  g_kv);
    cudaGetSymbolAddress((void**)&off,  g_off);
    cudaGetSymbolAddress((void**)&aoh,  g_aoh);
    cudaGetSymbolAddress((void**)&aol,  g_aol);
    cudaGetSymbolAddress((void**)&wqTh, g_wqTh);
    cudaGetSymbolAddress((void**)&wqTl, g_wqTl);
    cudaGetSymbolAddress((void**)&wkvTh, g_wkvTh);
    cudaGetSymbolAddress((void**)&wkvTl, g_wkvTl);
    cudaGetSymbolAddress((void**)&wouth, g_wouth);
    cudaGetSymbolAddress((void**)&woutl, g_woutl);
    cudaGetSymbolAddress((void**)&biasq,  g_biasq);
    cudaGetSymbolAddress((void**)&biaskv, g_biaskv);

    cudaFuncSetAttribute(bf16x3_gemm<1>, cudaFuncAttributeMaxDynamicSharedMemorySize, GEMM_SMEM);

    float* out_main = (float*)d_out;
    float* out_off  = out_main + (size_t)MQ * DIMc;

    // weight prep: gamma-folded transposed planes + beta-folded biases
    transpose_split_scale<<<dim3(INNERc/32, INNERc/32), dim3(32,8)>>>(Wq, lnqg, wqTh, wqTl, INNERc, INNERc);
    transpose_split_scale<<<dim3(INNERc/32, DIMc/32),   dim3(32,8)>>>(Wk, lnkg, wkvTh, wkvTl, DIMc, INNERc);
    transpose_split_scale<<<dim3(INNERc/32, DIMc/32),   dim3(32,8)>>>(Wv, lnvg,
        wkvTh + (size_t)INNERc*DIMc, wkvTl + (size_t)INNERc*DIMc, DIMc, INNERc);
    split_kernel<<<(DIMc*INNERc + 255)/256, 256>>>(Wout, wouth, woutl, DIMc*INNERc);
    fold_bias<<<2, 256>>>(Wq, lnqb, nullptr, biasq, INNERc, INNERc);
    fold_bias<<<2, 256>>>(Wk, lnkb, bk, biaskv, DIMc, INNERc);
    fold_bias<<<2, 256>>>(Wv, lnvb, bv, biaskv + INNERc, DIMc, INNERc);

    lnq_kernel <<<MQ, 256>>>(x, px, qlnh, qlnl);
    lnkv_kernel<<<MKV, 256>>>(x, px, nh, nl);

    // q = nrm_q @ foldedWq + biasq
    bf16x3_gemm<1><<<dim3(INNERc/128, MQ/128),  256, GEMM_SMEM>>>(qlnh, qlnl, wqTh, wqTl, biasq, qb, INNERc, INNERc);
    // kv = nrm @ [foldedWk | foldedWv] + biaskv   (Ntot=1024)
    bf16x3_gemm<1><<<dim3(2*INNERc/128, MKV/128), 256, GEMM_SMEM>>>(nh, nl, wkvTh, wkvTl, biaskv, kvb, 2*INNERc, DIMc);

    off_kernel<<<MQ/128, 128>>>(qb, Woff, boff, off, out_off);
    attn_kernel<<<(MQ*Hh)/8, 256>>>(qb, kvb, off, aoh, aol);

    // out = ao @ Wout^T + bout
    bf16x3_gemm<1><<<dim3(DIMc/128, MQ/128), 256, GEMM_SMEM>>>(aoh, aol, wouth, woutl, bout, out_main, DIMc, INNERc);
}

// round 6
// speedup vs baseline: 1.1335x; 1.1335x over previous
#include <cuda_runtime.h>
#include <cuda_bf16.h>
#include <cstdint>
#include <math.h>

#define Bsz 4
#define Nn 4096
#define DIMc 256
#define Hh 8
#define DHd 64
#define Pp 2
#define INNERc 512
#define MQ (Bsz*Nn)      /* 16384 */
#define MKV (2*Bsz*Nn)   /* 32768 */

typedef __nv_bfloat16 bf16;

// ---------------- scratch (device globals) ----------------
__device__ bf16  g_qlnh[MQ * INNERc];
__device__ bf16  g_qlnl[MQ * INNERc];
__device__ float g_q   [MQ * INNERc];
__device__ bf16  g_nh  [MKV * DIMc];       // LN(kv) normalized, hi
__device__ bf16  g_nl  [MKV * DIMc];       // LN(kv) normalized, lo
__device__ float g_kv  [MKV * 2 * INNERc]; // fused k|v output [row, 1024]
__device__ bf16  g_aoh [MQ * INNERc];
__device__ bf16  g_aol [MQ * INNERc];
__device__ bf16  g_wqTh[INNERc * INNERc];
__device__ bf16  g_wqTl[INNERc * INNERc];
__device__ bf16  g_wkvTh[2 * INNERc * DIMc];  // [1024, 256]
__device__ bf16  g_wkvTl[2 * INNERc * DIMc];
__device__ bf16  g_wouth[DIMc * INNERc];
__device__ bf16  g_woutl[DIMc * INNERc];
__device__ float g_biasq [INNERc];
__device__ float g_biaskv[2 * INNERc];

// ================= helpers =================
__device__ __forceinline__ uint32_t smem_u32(const void* p){
    uint32_t a;
    asm("{ .reg .u64 t; cvta.to.shared.u64 t, %1; cvt.u32.u64 %0, t; }" : "=r"(a) : "l"(p));
    return a;
}
__device__ __forceinline__ void bsplit(float v, bf16& h, bf16& l){
    h = __float2bfloat16(v);
    l = __float2bfloat16(v - __bfloat162float(h));
}
__device__ __forceinline__ void mma_bf16(float d[4], const uint32_t a[4], const uint32_t b[2]){
    asm volatile("mma.sync.aligned.m16n8k16.row.col.f32.bf16.bf16.f32 "
        "{%0,%1,%2,%3}, {%4,%5,%6,%7}, {%8,%9}, {%0,%1,%2,%3};"
        : "+f"(d[0]),"+f"(d[1]),"+f"(d[2]),"+f"(d[3])
        : "r"(a[0]),"r"(a[1]),"r"(a[2]),"r"(a[3]),"r"(b[0]),"r"(b[1]));
}
__device__ __forceinline__ void ldsm4(uint32_t r[4], uint32_t addr){
    asm volatile("ldmatrix.sync.aligned.m8n8.x4.shared.b16 {%0,%1,%2,%3}, [%4];"
        : "=r"(r[0]),"=r"(r[1]),"=r"(r[2]),"=r"(r[3]) : "r"(addr));
}
__device__ __forceinline__ void cp16(uint32_t dst, const void* src){
    asm volatile("cp.async.cg.shared.global [%0], [%1], 16;" :: "r"(dst), "l"(src));
}

// ================= bf16x3 tensor-core GEMM =================
// C[M,Ntot] = (Ah+Al)[M,K] @ (Bh+Bl)[Ntot,K]^T (+bias), x3 terms.
// 256 thr, tile 128x128, K-chunk 32, 4-stage cp.async (depth 3), 1 sync/chunk.
#define TILE_B 10240
#define STAGE_B 40960
#define GEMM_SMEM (4*STAGE_B)

template<int HAS_BIAS>
__global__ void __launch_bounds__(256, 1)
bf16x3_gemm(const bf16* __restrict__ Ah, const bf16* __restrict__ Al,
            const bf16* __restrict__ Bh, const bf16* __restrict__ Bl,
            const float* __restrict__ bias, float* __restrict__ C,
            int Ntot, int K)
{
    extern __shared__ char smem[];
    const uint32_t sb = smem_u32(smem);
    const int tid = threadIdx.x, lane = tid & 31, wid = tid >> 5;
    const int wm = wid >> 2, wn = wid & 3;         // 2x4 warp grid, 64x32 per warp
    const int bm = blockIdx.y * 128, bn = blockIdx.x * 128;
    const int NC = K >> 5;

    const int lr  = tid >> 2;       // 0..63
    const int lcc = tid & 3;        // 16B chunk within 32-k row segment

    auto load_stage = [&](int buf, int kc){
        uint32_t sbase = sb + buf * STAGE_B + lr * 80 + lcc * 16;
        size_t ao = (size_t)(bm + lr) * K + kc + lcc * 8;
        size_t bo = (size_t)(bn + lr) * K + kc + lcc * 8;
        size_t row64 = (size_t)64 * K;
        cp16(sbase,                    Ah + ao);
        cp16(sbase + 64*80,            Ah + ao + row64);
        cp16(sbase + TILE_B,           Al + ao);
        cp16(sbase + TILE_B + 64*80,   Al + ao + row64);
        cp16(sbase + 2*TILE_B,         Bh + bo);
        cp16(sbase + 2*TILE_B + 64*80, Bh + bo + row64);
        cp16(sbase + 3*TILE_B,         Bl + bo);
        cp16(sbase + 3*TILE_B + 64*80, Bl + bo + row64);
        asm volatile("cp.async.commit_group;" ::: "memory");
    };

    float acc[4][4][4] = {};
    const uint32_t arow = (uint32_t)(lane & 15) * 80 + (uint32_t)(lane >> 4) * 16;

    auto compute = [&](int buf){
        uint32_t base = sb + buf * STAGE_B;
        #pragma unroll
        for (int ks = 0; ks < 2; ks++){
            uint32_t ah[4][4], al_[4][4], bh[4][2], bl[4][2];
            #pragma unroll
            for (int i = 0; i < 4; i++){
                uint32_t a = base + (uint32_t)(wm*64 + i*16) * 80 + arow + ks*32;
                ldsm4(ah[i],  a);
                ldsm4(al_[i], a + TILE_B);
            }
            #pragma unroll
            for (int jp = 0; jp < 2; jp++){
                uint32_t a = base + 2*TILE_B + (uint32_t)(wn*32 + jp*16) * 80 + arow + ks*32;
                uint32_t r4[4];
                ldsm4(r4, a);
                bh[jp*2][0]=r4[0]; bh[jp*2+1][0]=r4[1]; bh[jp*2][1]=r4[2]; bh[jp*2+1][1]=r4[3];
                ldsm4(r4, a + TILE_B);
                bl[jp*2][0]=r4[0]; bl[jp*2+1][0]=r4[1]; bl[jp*2][1]=r4[2]; bl[jp*2+1][1]=r4[3];
            }
            #pragma unroll
            for (int i = 0; i < 4; i++)
                #pragma unroll
                for (int j = 0; j < 4; j++){
                    mma_bf16(acc[i][j], ah[i],  bh[j]);
                    mma_bf16(acc[i][j], ah[i],  bl[j]);
                    mma_bf16(acc[i][j], al_[i], bh[j]);
                }
        }
    };

    load_stage(0, 0);
    load_stage(1, 32);
    load_stage(2, 64);

    for (int c = 0; c < NC; c++){
        if (c <= NC - 3)      asm volatile("cp.async.wait_group 2;" ::: "memory");
        else if (c == NC - 2) asm volatile("cp.async.wait_group 1;" ::: "memory");
        else                  asm volatile("cp.async.wait_group 0;" ::: "memory");
        __syncthreads();
        if (c + 3 < NC) load_stage((c + 3) & 3, (c + 3) * 32);
        compute(c & 3);
    }

    #pragma unroll
    for (int i = 0; i < 4; i++){
        int r0 = bm + wm*64 + i*16 + (lane >> 2);
        #pragma unroll
        for (int j = 0; j < 4; j++){
            int c0 = bn + wn*32 + j*8 + (lane & 3)*2;
            float b0 = 0.f, b1 = 0.f;
            if (HAS_BIAS){ b0 = bias[c0]; b1 = bias[c0+1]; }
            *(float2*)(C + (size_t)r0 * Ntot + c0)     = make_float2(acc[i][j][0]+b0, acc[i][j][1]+b1);
            *(float2*)(C + (size_t)(r0+8) * Ntot + c0) = make_float2(acc[i][j][2]+b0, acc[i][j][3]+b1);
        }
    }
}

// ========= transpose + gamma-fold + split: out[n,k] = split(g[k]*W[k,n]) =========
__global__ void transpose_split_scale(const float* __restrict__ in, const float* __restrict__ g,
                                      bf16* __restrict__ oh, bf16* __restrict__ ol,
                                      int R, int C){
    __shared__ float tile[32][33];
    int c0 = blockIdx.x * 32, r0 = blockIdx.y * 32;
    int tx = threadIdx.x, ty = threadIdx.y;
    #pragma unroll
    for (int i = 0; i < 32; i += 8){
        int r = r0 + ty + i;
        tile[ty + i][tx] = in[(size_t)r * C + c0 + tx] * g[r];
    }
    __syncthreads();
    #pragma unroll
    for (int i = 0; i < 32; i += 8){
        float v = tile[tx][ty + i];
        bf16 h, l; bsplit(v, h, l);
        size_t o = (size_t)(c0 + ty + i) * R + r0 + tx;
        oh[o] = h; ol[o] = l;
    }
}

// ========= bias fold (warp per column): out[n] = base[n] + sum_k beta[k]*W[k,n] ======
__global__ void fold_bias(const float* __restrict__ W, const float* __restrict__ beta,
                          const float* __restrict__ base, float* __restrict__ out,
                          int K, int N){
    int n = blockIdx.x;               // one warp-block per output column
    int lane = threadIdx.x;           // 32 threads
    float s = 0.f;
    for (int k = lane; k < K; k += 32) s += beta[k] * W[(size_t)k * N + n];
    #pragma unroll
    for (int o = 16; o > 0; o >>= 1) s += __shfl_xor_sync(0xffffffffu, s, o);
    if (lane == 0) out[n] = s + (base ? base[n] : 0.f);
}

// ================= elementwise split (Wout) =================
__global__ void split_kernel(const float* __restrict__ in,
                             bf16* __restrict__ oh, bf16* __restrict__ ol, int n){
    int i = blockIdx.x * blockDim.x + threadIdx.x;
    if (i >= n) return;
    bf16 h, l; bsplit(in[i], h, l);
    oh[i] = h; ol[i] = l;
}

// ================= block reduce =================
__device__ __forceinline__ float2 blockReduce2(float a, float b) {
    __shared__ float2 sbuf[8];
    #pragma unroll
    for (int o = 16; o > 0; o >>= 1) {
        a += __shfl_xor_sync(0xffffffffu, a, o);
        b += __shfl_xor_sync(0xffffffffu, b, o);
    }
    int w = threadIdx.x >> 5;
    if ((threadIdx.x & 31) == 0) sbuf[w] = make_float2(a, b);
    __syncthreads();
    if (w == 0) {
        int nw = blockDim.x >> 5;
        float2 r = (threadIdx.x < nw) ? sbuf[threadIdx.x] : make_float2(0.f, 0.f);
        #pragma unroll
        for (int o = 4; o > 0; o >>= 1) {
            r.x += __shfl_xor_sync(0xffffffffu, r.x, o);
            r.y += __shfl_xor_sync(0xffffffffu, r.y, o);
        }
        if (threadIdx.x == 0) sbuf[0] = r;
    }
    __syncthreads();
    return sbuf[0];
}

// ============ LN over concat (512) — emits PLAIN normalized planes ============
__global__ void lnq_kernel(const float* __restrict__ x, const float* __restrict__ px,
                           bf16* __restrict__ oh, bf16* __restrict__ ol) {
    int row = blockIdx.x;
    int t = threadIdx.x;
    float v0 = x [row * DIMc + t];
    float v1 = px[row * DIMc + t];
    float2 r = blockReduce2(v0 + v1, v0 * v0 + v1 * v1);
    float mean = r.x * (1.0f / 512.0f);
    float var  = r.y * (1.0f / 512.0f) - mean * mean;
    float rstd = rsqrtf(var + 1e-5f);
    bf16 h, l;
    bsplit((v0 - mean) * rstd, h, l); oh[row * INNERc + t] = h;       ol[row * INNERc + t] = l;
    bsplit((v1 - mean) * rstd, h, l); oh[row * INNERc + 256 + t] = h; ol[row * INNERc + 256 + t] = l;
}

// ============ LN over kv (256) — single normalized plane pair ============
__global__ void lnkv_kernel(const float* __restrict__ x, const float* __restrict__ px,
                            bf16* __restrict__ nh, bf16* __restrict__ nl) {
    int row = blockIdx.x;
    int t = threadIdx.x;
    const float* src = (row < Bsz * Nn) ? x : px;
    int r2 = (row < Bsz * Nn) ? row : row - Bsz * Nn;
    float v = src[r2 * DIMc + t];
    float2 r = blockReduce2(v, v * v);
    float mean = r.x * (1.0f / 256.0f);
    float var  = r.y * (1.0f / 256.0f) - mean * mean;
    float rstd = rsqrtf(var + 1e-5f);
    bf16 h, l;
    bsplit((v - mean) * rstd, h, l);
    nh[row * DIMc + t] = h; nl[row * DIMc + t] = l;
}

// ============ offsets projection (fp32) — writes transposed (B,H,P,N) only =====
__global__ void off_kernel(const float* __restrict__ q, const float* __restrict__ Woff,
                           const float* __restrict__ boff, float* __restrict__ off_out) {
    __shared__ float w[16][INNERc];
    int tid = threadIdx.x;
    for (int i = tid; i < 16 * INNERc; i += 128) w[i >> 9][i & 511] = Woff[i];
    __syncthreads();
    int m = blockIdx.x * 128 + tid;        // b*N + n
    const float* qr = q + (size_t)m * INNERc;
    float acc[16];
    #pragma unroll
    for (int j = 0; j < 16; j++) acc[j] = boff[j];
    for (int k0 = 0; k0 < INNERc; k0 += 4){
        float4 qv = *(const float4*)(qr + k0);
        #pragma unroll
        for (int j = 0; j < 16; j++)
            acc[j] += qv.x * w[j][k0] + qv.y * w[j][k0+1] + qv.z * w[j][k0+2] + qv.w * w[j][k0+3];
    }
    int b = m >> 12, n = m & 4095;
    #pragma unroll
    for (int j = 0; j < 16; j++)
        off_out[((size_t)(b * 16 + j)) * Nn + n] = acc[j];
}

// ================= attention (fused KV layout [row,1024]) =================
// reads offsets from the transposed (B,H,P,N) buffer
__global__ void attn_kernel(const float* __restrict__ q, const float* __restrict__ kv,
                            const float* __restrict__ off_t,
                            bf16* __restrict__ aoh, bf16* __restrict__ aol) {
    int gw = (blockIdx.x * blockDim.x + threadIdx.x) >> 5;
    int lane = threadIdx.x & 31;
    if (gw >= MQ * Hh) return;
    int bn = gw / Hh;
    int h  = gw - bn * Hh;
    int b  = bn / Nn;
    int n  = bn - b * Nn;

    float o0 = off_t[((size_t)(b * 16 + h * Pp + 0)) * Nn + n];
    float o1 = off_t[((size_t)(b * 16 + h * Pp + 1)) * Nn + n];
    float t0 = fminf(fmaxf((float)n + o0, 0.f), (float)(2 * Nn - 1));
    float t1 = fminf(fmaxf((float)n + o1, 0.f), (float)(2 * Nn - 1));
    int j0 = (int)t0, j1 = (int)t1;
    int s0 = (j0 >= Nn) ? 1 : 0; int np0 = j0 - s0 * Nn;
    int s1 = (j1 >= Nn) ? 1 : 0; int np1 = j1 - s1 * Nn;

    const float* qb  = q + (size_t)bn * INNERc + h * DHd;
    const float* r0p = kv + ((size_t)(s0 * Bsz + b) * Nn + np0) * (2*INNERc) + h * DHd;
    const float* r1p = kv + ((size_t)(s1 * Bsz + b) * Nn + np1) * (2*INNERc) + h * DHd;

    float qa = qb[lane], qc = qb[lane + 32];
    float d0 = qa * r0p[lane] + qc * r0p[lane + 32];
    float d1 = qa * r1p[lane] + qc * r1p[lane + 32];
    #pragma unroll
    for (int o = 16; o > 0; o >>= 1) {
        d0 += __shfl_xor_sync(0xffffffffu, d0, o);
        d1 += __shfl_xor_sync(0xffffffffu, d1, o);
    }
    const float scale = 0.125f;
    d0 *= scale; d1 *= scale;
    float mx = fmaxf(d0, d1);
    float e0 = __expf(d0 - mx), e1 = __expf(d1 - mx);
    float inv = 1.0f / (e0 + e1);
    float a0 = e0 * inv, a1 = e1 * inv;

    const float* v0p = r0p + INNERc;
    const float* v1p = r1p + INNERc;
    float r0 = a0 * v0p[lane]      + a1 * v1p[lane];
    float r1 = a0 * v0p[lane + 32] + a1 * v1p[lane + 32];
    bf16 hh, ll;
    size_t o_base = (size_t)bn * INNERc + h * DHd;
    bsplit(r0, hh, ll); aoh[o_base + lane]      = hh; aol[o_base + lane]      = ll;
    bsplit(r1, hh, ll); aoh[o_base + lane + 32] = hh; aol[o_base + lane + 32] = ll;
}

// ================= launch =================
extern "C" void kernel_launch(void* const* d_in, const int* in_sizes, int n_in,
                              void* d_out, int out_size) {
    const float* x     = (const float*)d_in[0];
    const float* px    = (const float*)d_in[1];
    const float* lnqg  = (const float*)d_in[2];
    const float* lnqb  = (const float*)d_in[3];
    const float* lnkg  = (const float*)d_in[4];
    const float* lnkb  = (const float*)d_in[5];
    const float* lnvg  = (const float*)d_in[6];
    const float* lnvb  = (const float*)d_in[7];
    const float* Wq    = (const float*)d_in[8];
    const float* Wk    = (const float*)d_in[9];
    const float* bk    = (const float*)d_in[10];
    const float* Wv    = (const float*)d_in[11];
    const float* bv    = (const float*)d_in[12];
    const float* Woff  = (const float*)d_in[13];
    const float* boff  = (const float*)d_in[14];
    const float* Wout  = (const float*)d_in[15];
    const float* bout  = (const float*)d_in[16];

    bf16 *qlnh,*qlnl,*nh,*nl,*aoh,*aol;
    bf16 *wqTh,*wqTl,*wkvTh,*wkvTl,*wouth,*woutl;
    float *qb,*kvb,*biasq,*biaskv;
    cudaGetSymbolAddress((void**)&qlnh, g_qlnh);
    cudaGetSymbolAddress((void**)&qlnl, g_qlnl);
    cudaGetSymbolAddress((void**)&qb,   g_q);
    cudaGetSymbolAddress((void**)&nh,   g_nh);
    cudaGetSymbolAddress((void**)&nl,   g_nl);
    cudaGetSymbolAddress((void**)&kvb,  g_kv);
    cudaGetSymbolAddress((void**)&aoh,  g_aoh);
    cudaGetSymbolAddress((void**)&aol,  g_aol);
    cudaGetSymbolAddress((void**)&wqTh, g_wqTh);
    cudaGetSymbolAddress((void**)&wqTl, g_wqTl);
    cudaGetSymbolAddress((void**)&wkvTh, g_wkvTh);
    cudaGetSymbolAddress((void**)&wkvTl, g_wkvTl);
    cudaGetSymbolAddress((void**)&wouth, g_wouth);
    cudaGetSymbolAddress((void**)&woutl, g_woutl);
    cudaGetSymbolAddress((void**)&biasq,  g_biasq);
    cudaGetSymbolAddress((void**)&biaskv, g_biaskv);

    cudaFuncSetAttribute(bf16x3_gemm<1>, cudaFuncAttributeMaxDynamicSharedMemorySize, GEMM_SMEM);

    float* out_main = (float*)d_out;
    float* out_off  = out_main + (size_t)MQ * DIMc;

    // weight prep: gamma-folded transposed planes + beta-folded biases
    transpose_split_scale<<<dim3(INNERc/32, INNERc/32), dim3(32,8)>>>(Wq, lnqg, wqTh, wqTl, INNERc, INNERc);
    transpose_split_scale<<<dim3(INNERc/32, DIMc/32),   dim3(32,8)>>>(Wk, lnkg, wkvTh, wkvTl, DIMc, INNERc);
    transpose_split_scale<<<dim3(INNERc/32, DIMc/32),   dim3(32,8)>>>(Wv, lnvg,
        wkvTh + (size_t)INNERc*DIMc, wkvTl + (size_t)INNERc*DIMc, DIMc, INNERc);
    split_kernel<<<(DIMc*INNERc + 255)/256, 256>>>(Wout, wouth, woutl, DIMc*INNERc);
    fold_bias<<<INNERc, 32>>>(Wq, lnqb, nullptr, biasq, INNERc, INNERc);
    fold_bias<<<INNERc, 32>>>(Wk, lnkb, bk, biaskv, DIMc, INNERc);
    fold_bias<<<INNERc, 32>>>(Wv, lnvb, bv, biaskv + INNERc, DIMc, INNERc);

    lnq_kernel <<<MQ, 256>>>(x, px, qlnh, qlnl);
    lnkv_kernel<<<MKV, 256>>>(x, px, nh, nl);

    // q = nrm_q @ foldedWq + biasq
    bf16x3_gemm<1><<<dim3(INNERc/128, MQ/128),  256, GEMM_SMEM>>>(qlnh, qlnl, wqTh, wqTl, biasq, qb, INNERc, INNERc);
    // kv = nrm @ [foldedWk | foldedWv] + biaskv   (Ntot=1024)
    bf16x3_gemm<1><<<dim3(2*INNERc/128, MKV/128), 256, GEMM_SMEM>>>(nh, nl, wkvTh, wkvTl, biaskv, kvb, 2*INNERc, DIMc);

    off_kernel<<<MQ/128, 128>>>(qb, Woff, boff, out_off);
    attn_kernel<<<(MQ*Hh)/8, 256>>>(qb, kvb, out_off, aoh, aol);

    // out = ao @ Wout^T + bout
    bf16x3_gemm<1><<<dim3(DIMc/128, MQ/128), 256, GEMM_SMEM>>>(aoh, aol, wouth, woutl, bout, out_main, DIMc, INNERc);
}

// round 7
// speedup vs baseline: 1.2379x; 1.0921x over previous
#include <cuda_runtime.h>
#include <cuda_bf16.h>
#include <cstdint>
#include <math.h>

#define Bsz 4
#define Nn 4096
#define DIMc 256
#define Hh 8
#define DHd 64
#define Pp 2
#define INNERc 512
#define MQ (Bsz*Nn)      /* 16384 */
#define MKV (2*Bsz*Nn)   /* 32768 */

typedef __nv_bfloat16 bf16;

// ---------------- scratch (device globals) ----------------
__device__ bf16  g_qlnh[MQ * INNERc];
__device__ bf16  g_qlnl[MQ * INNERc];
__device__ float g_q   [MQ * INNERc];
__device__ bf16  g_nh  [MKV * DIMc];       // LN(kv) normalized, hi
__device__ bf16  g_nl  [MKV * DIMc];       // LN(kv) normalized, lo
__device__ float g_kv  [MKV * 2 * INNERc]; // fused k|v output [row, 1024]
__device__ bf16  g_aoh [MQ * INNERc];
__device__ bf16  g_aol [MQ * INNERc];
__device__ bf16  g_wqTh[INNERc * INNERc];
__device__ bf16  g_wqTl[INNERc * INNERc];
__device__ bf16  g_wkvTh[2 * INNERc * DIMc];  // [1024, 256]
__device__ bf16  g_wkvTl[2 * INNERc * DIMc];
__device__ bf16  g_wouth[DIMc * INNERc];
__device__ bf16  g_woutl[DIMc * INNERc];
__device__ float g_biasq [INNERc];
__device__ float g_biaskv[2 * INNERc];

// ================= helpers =================
__device__ __forceinline__ uint32_t smem_u32(const void* p){
    uint32_t a;
    asm("{ .reg .u64 t; cvta.to.shared.u64 t, %1; cvt.u32.u64 %0, t; }" : "=r"(a) : "l"(p));
    return a;
}
__device__ __forceinline__ void bsplit(float v, bf16& h, bf16& l){
    h = __float2bfloat16(v);
    l = __float2bfloat16(v - __bfloat162float(h));
}
__device__ __forceinline__ void mma_bf16(float d[4], const uint32_t a[4], const uint32_t b[2]){
    asm volatile("mma.sync.aligned.m16n8k16.row.col.f32.bf16.bf16.f32 "
        "{%0,%1,%2,%3}, {%4,%5,%6,%7}, {%8,%9}, {%0,%1,%2,%3};"
        : "+f"(d[0]),"+f"(d[1]),"+f"(d[2]),"+f"(d[3])
        : "r"(a[0]),"r"(a[1]),"r"(a[2]),"r"(a[3]),"r"(b[0]),"r"(b[1]));
}
__device__ __forceinline__ void ldsm4(uint32_t r[4], uint32_t addr){
    asm volatile("ldmatrix.sync.aligned.m8n8.x4.shared.b16 {%0,%1,%2,%3}, [%4];"
        : "=r"(r[0]),"=r"(r[1]),"=r"(r[2]),"=r"(r[3]) : "r"(addr));
}
__device__ __forceinline__ void cp16(uint32_t dst, const void* src){
    asm volatile("cp.async.cg.shared.global [%0], [%1], 16;" :: "r"(dst), "l"(src));
}

// ================= bf16x3 tensor-core GEMM =================
// C[M,Ntot] = (Ah+Al)[M,K] @ (Bh+Bl)[Ntot,K]^T (+bias), x3 terms.
// 256 thr, tile 128x128, K-chunk 32, 2-stage cp.async, 2 CTAs/SM (80KB smem).
#define TILE_B 10240
#define STAGE_B 40960
#define GEMM_SMEM (2*STAGE_B)

template<int HAS_BIAS>
__global__ void __launch_bounds__(256, 2)
bf16x3_gemm(const bf16* __restrict__ Ah, const bf16* __restrict__ Al,
            const bf16* __restrict__ Bh, const bf16* __restrict__ Bl,
            const float* __restrict__ bias, float* __restrict__ C,
            int Ntot, int K)
{
    extern __shared__ char smem[];
    const uint32_t sb = smem_u32(smem);
    const int tid = threadIdx.x, lane = tid & 31, wid = tid >> 5;
    const int wm = wid >> 2, wn = wid & 3;         // 2x4 warp grid, 64x32 per warp
    const int bm = blockIdx.y * 128, bn = blockIdx.x * 128;
    const int NC = K >> 5;

    const int lr  = tid >> 2;       // 0..63
    const int lcc = tid & 3;        // 16B chunk within 32-k row segment

    auto load_stage = [&](int buf, int kc){
        uint32_t sbase = sb + buf * STAGE_B + lr * 80 + lcc * 16;
        size_t ao = (size_t)(bm + lr) * K + kc + lcc * 8;
        size_t bo = (size_t)(bn + lr) * K + kc + lcc * 8;
        size_t row64 = (size_t)64 * K;
        cp16(sbase,                    Ah + ao);
        cp16(sbase + 64*80,            Ah + ao + row64);
        cp16(sbase + TILE_B,           Al + ao);
        cp16(sbase + TILE_B + 64*80,   Al + ao + row64);
        cp16(sbase + 2*TILE_B,         Bh + bo);
        cp16(sbase + 2*TILE_B + 64*80, Bh + bo + row64);
        cp16(sbase + 3*TILE_B,         Bl + bo);
        cp16(sbase + 3*TILE_B + 64*80, Bl + bo + row64);
        asm volatile("cp.async.commit_group;" ::: "memory");
    };

    float acc[4][4][4] = {};
    const uint32_t arow = (uint32_t)(lane & 15) * 80 + (uint32_t)(lane >> 4) * 16;

    auto compute = [&](int buf){
        uint32_t base = sb + buf * STAGE_B;
        #pragma unroll
        for (int ks = 0; ks < 2; ks++){
            uint32_t ah[4][4], al_[4][4];
            #pragma unroll
            for (int i = 0; i < 4; i++){
                uint32_t a = base + (uint32_t)(wm*64 + i*16) * 80 + arow + ks*32;
                ldsm4(ah[i],  a);
                ldsm4(al_[i], a + TILE_B);
            }
            #pragma unroll
            for (int jp = 0; jp < 2; jp++){
                uint32_t a = base + 2*TILE_B + (uint32_t)(wn*32 + jp*16) * 80 + arow + ks*32;
                uint32_t bh0[2], bh1[2], bl0[2], bl1[2], r4[4];
                ldsm4(r4, a);
                bh0[0]=r4[0]; bh1[0]=r4[1]; bh0[1]=r4[2]; bh1[1]=r4[3];
                ldsm4(r4, a + TILE_B);
                bl0[0]=r4[0]; bl1[0]=r4[1]; bl0[1]=r4[2]; bl1[1]=r4[3];
                #pragma unroll
                for (int i = 0; i < 4; i++){
                    mma_bf16(acc[i][jp*2],   ah[i],  bh0);
                    mma_bf16(acc[i][jp*2],   ah[i],  bl0);
                    mma_bf16(acc[i][jp*2],   al_[i], bh0);
                    mma_bf16(acc[i][jp*2+1], ah[i],  bh1);
                    mma_bf16(acc[i][jp*2+1], ah[i],  bl1);
                    mma_bf16(acc[i][jp*2+1], al_[i], bh1);
                }
            }
        }
    };

    load_stage(0, 0);
    load_stage(1, 32);

    for (int c = 0; c < NC; c++){
        if (c < NC - 1) asm volatile("cp.async.wait_group 1;" ::: "memory");
        else            asm volatile("cp.async.wait_group 0;" ::: "memory");
        __syncthreads();
        compute(c & 1);
        __syncthreads();
        if (c + 2 < NC) load_stage(c & 1, (c + 2) * 32);
    }

    #pragma unroll
    for (int i = 0; i < 4; i++){
        int r0 = bm + wm*64 + i*16 + (lane >> 2);
        #pragma unroll
        for (int j = 0; j < 4; j++){
            int c0 = bn + wn*32 + j*8 + (lane & 3)*2;
            float b0 = 0.f, b1 = 0.f;
            if (HAS_BIAS){ b0 = bias[c0]; b1 = bias[c0+1]; }
            *(float2*)(C + (size_t)r0 * Ntot + c0)     = make_float2(acc[i][j][0]+b0, acc[i][j][1]+b1);
            *(float2*)(C + (size_t)(r0+8) * Ntot + c0) = make_float2(acc[i][j][2]+b0, acc[i][j][3]+b1);
        }
    }
}

// ========= transpose + gamma-fold + split: out[n,k] = split(g[k]*W[k,n]) =========
__global__ void transpose_split_scale(const float* __restrict__ in, const float* __restrict__ g,
                                      bf16* __restrict__ oh, bf16* __restrict__ ol,
                                      int R, int C){
    __shared__ float tile[32][33];
    int c0 = blockIdx.x * 32, r0 = blockIdx.y * 32;
    int tx = threadIdx.x, ty = threadIdx.y;
    #pragma unroll
    for (int i = 0; i < 32; i += 8){
        int r = r0 + ty + i;
        tile[ty + i][tx] = in[(size_t)r * C + c0 + tx] * g[r];
    }
    __syncthreads();
    #pragma unroll
    for (int i = 0; i < 32; i += 8){
        float v = tile[tx][ty + i];
        bf16 h, l; bsplit(v, h, l);
        size_t o = (size_t)(c0 + ty + i) * R + r0 + tx;
        oh[o] = h; ol[o] = l;
    }
}

// ========= bias fold (warp per column): out[n] = base[n] + sum_k beta[k]*W[k,n] ======
__global__ void fold_bias(const float* __restrict__ W, const float* __restrict__ beta,
                          const float* __restrict__ base, float* __restrict__ out,
                          int K, int N){
    int n = blockIdx.x;               // one warp-block per output column
    int lane = threadIdx.x;           // 32 threads
    float s = 0.f;
    for (int k = lane; k < K; k += 32) s += beta[k] * W[(size_t)k * N + n];
    #pragma unroll
    for (int o = 16; o > 0; o >>= 1) s += __shfl_xor_sync(0xffffffffu, s, o);
    if (lane == 0) out[n] = s + (base ? base[n] : 0.f);
}

// ================= elementwise split (Wout) =================
__global__ void split_kernel(const float* __restrict__ in,
                             bf16* __restrict__ oh, bf16* __restrict__ ol, int n){
    int i = blockIdx.x * blockDim.x + threadIdx.x;
    if (i >= n) return;
    bf16 h, l; bsplit(in[i], h, l);
    oh[i] = h; ol[i] = l;
}

// ================= block reduce =================
__device__ __forceinline__ float2 blockReduce2(float a, float b) {
    __shared__ float2 sbuf[8];
    #pragma unroll
    for (int o = 16; o > 0; o >>= 1) {
        a += __shfl_xor_sync(0xffffffffu, a, o);
        b += __shfl_xor_sync(0xffffffffu, b, o);
    }
    int w = threadIdx.x >> 5;
    if ((threadIdx.x & 31) == 0) sbuf[w] = make_float2(a, b);
    __syncthreads();
    if (w == 0) {
        int nw = blockDim.x >> 5;
        float2 r = (threadIdx.x < nw) ? sbuf[threadIdx.x] : make_float2(0.f, 0.f);
        #pragma unroll
        for (int o = 4; o > 0; o >>= 1) {
            r.x += __shfl_xor_sync(0xffffffffu, r.x, o);
            r.y += __shfl_xor_sync(0xffffffffu, r.y, o);
        }
        if (threadIdx.x == 0) sbuf[0] = r;
    }
    __syncthreads();
    return sbuf[0];
}

// ============ LN over concat (512) — emits PLAIN normalized planes ============
__global__ void lnq_kernel(const float* __restrict__ x, const float* __restrict__ px,
                           bf16* __restrict__ oh, bf16* __restrict__ ol) {
    int row = blockIdx.x;
    int t = threadIdx.x;
    float v0 = x [row * DIMc + t];
    float v1 = px[row * DIMc + t];
    float2 r = blockReduce2(v0 + v1, v0 * v0 + v1 * v1);
    float mean = r.x * (1.0f / 512.0f);
    float var  = r.y * (1.0f / 512.0f) - mean * mean;
    float rstd = rsqrtf(var + 1e-5f);
    bf16 h, l;
    bsplit((v0 - mean) * rstd, h, l); oh[row * INNERc + t] = h;       ol[row * INNERc + t] = l;
    bsplit((v1 - mean) * rstd, h, l); oh[row * INNERc + 256 + t] = h; ol[row * INNERc + 256 + t] = l;
}

// ============ LN over kv (256) — single normalized plane pair ============
__global__ void lnkv_kernel(const float* __restrict__ x, const float* __restrict__ px,
                            bf16* __restrict__ nh, bf16* __restrict__ nl) {
    int row = blockIdx.x;
    int t = threadIdx.x;
    const float* src = (row < Bsz * Nn) ? x : px;
    int r2 = (row < Bsz * Nn) ? row : row - Bsz * Nn;
    float v = src[r2 * DIMc + t];
    float2 r = blockReduce2(v, v * v);
    float mean = r.x * (1.0f / 256.0f);
    float var  = r.y * (1.0f / 256.0f) - mean * mean;
    float rstd = rsqrtf(var + 1e-5f);
    bf16 h, l;
    bsplit((v - mean) * rstd, h, l);
    nh[row * DIMc + t] = h; nl[row * DIMc + t] = l;
}

// ============ offsets projection (fp32) — writes transposed (B,H,P,N) only =====
__global__ void off_kernel(const float* __restrict__ q, const float* __restrict__ Woff,
                           const float* __restrict__ boff, float* __restrict__ off_out) {
    __shared__ float w[16][INNERc];
    int tid = threadIdx.x;
    for (int i = tid; i < 16 * INNERc; i += 128) w[i >> 9][i & 511] = Woff[i];
    __syncthreads();
    int m = blockIdx.x * 128 + tid;        // b*N + n
    const float* qr = q + (size_t)m * INNERc;
    float acc[16];
    #pragma unroll
    for (int j = 0; j < 16; j++) acc[j] = boff[j];
    for (int k0 = 0; k0 < INNERc; k0 += 4){
        float4 qv = *(const float4*)(qr + k0);
        #pragma unroll
        for (int j = 0; j < 16; j++)
            acc[j] += qv.x * w[j][k0] + qv.y * w[j][k0+1] + qv.z * w[j][k0+2] + qv.w * w[j][k0+3];
    }
    int b = m >> 12, n = m & 4095;
    #pragma unroll
    for (int j = 0; j < 16; j++)
        off_out[((size_t)(b * 16 + j)) * Nn + n] = acc[j];
}

// ================= attention (fused KV layout [row,1024]) =================
__global__ void attn_kernel(const float* __restrict__ q, const float* __restrict__ kv,
                            const float* __restrict__ off_t,
                            bf16* __restrict__ aoh, bf16* __restrict__ aol) {
    int gw = (blockIdx.x * blockDim.x + threadIdx.x) >> 5;
    int lane = threadIdx.x & 31;
    if (gw >= MQ * Hh) return;
    int bn = gw / Hh;
    int h  = gw - bn * Hh;
    int b  = bn / Nn;
    int n  = bn - b * Nn;

    float o0 = off_t[((size_t)(b * 16 + h * Pp + 0)) * Nn + n];
    float o1 = off_t[((size_t)(b * 16 + h * Pp + 1)) * Nn + n];
    float t0 = fminf(fmaxf((float)n + o0, 0.f), (float)(2 * Nn - 1));
    float t1 = fminf(fmaxf((float)n + o1, 0.f), (float)(2 * Nn - 1));
    int j0 = (int)t0, j1 = (int)t1;
    int s0 = (j0 >= Nn) ? 1 : 0; int np0 = j0 - s0 * Nn;
    int s1 = (j1 >= Nn) ? 1 : 0; int np1 = j1 - s1 * Nn;

    const float* qb  = q + (size_t)bn * INNERc + h * DHd;
    const float* r0p = kv + ((size_t)(s0 * Bsz + b) * Nn + np0) * (2*INNERc) + h * DHd;
    const float* r1p = kv + ((size_t)(s1 * Bsz + b) * Nn + np1) * (2*INNERc) + h * DHd;

    float qa = qb[lane], qc = qb[lane + 32];
    float d0 = qa * r0p[lane] + qc * r0p[lane + 32];
    float d1 = qa * r1p[lane] + qc * r1p[lane + 32];
    #pragma unroll
    for (int o = 16; o > 0; o >>= 1) {
        d0 += __shfl_xor_sync(0xffffffffu, d0, o);
        d1 += __shfl_xor_sync(0xffffffffu, d1, o);
    }
    const float scale = 0.125f;
    d0 *= scale; d1 *= scale;
    float mx = fmaxf(d0, d1);
    float e0 = __expf(d0 - mx), e1 = __expf(d1 - mx);
    float inv = 1.0f / (e0 + e1);
    float a0 = e0 * inv, a1 = e1 * inv;

    const float* v0p = r0p + INNERc;
    const float* v1p = r1p + INNERc;
    float r0 = a0 * v0p[lane]      + a1 * v1p[lane];
    float r1 = a0 * v0p[lane + 32] + a1 * v1p[lane + 32];
    bf16 hh, ll;
    size_t o_base = (size_t)bn * INNERc + h * DHd;
    bsplit(r0, hh, ll); aoh[o_base + lane]      = hh; aol[o_base + lane]      = ll;
    bsplit(r1, hh, ll); aoh[o_base + lane + 32] = hh; aol[o_base + lane + 32] = ll;
}

// ================= launch =================
extern "C" void kernel_launch(void* const* d_in, const int* in_sizes, int n_in,
                              void* d_out, int out_size) {
    const float* x     = (const float*)d_in[0];
    const float* px    = (const float*)d_in[1];
    const float* lnqg  = (const float*)d_in[2];
    const float* lnqb  = (const float*)d_in[3];
    const float* lnkg  = (const float*)d_in[4];
    const float* lnkb  = (const float*)d_in[5];
    const float* lnvg  = (const float*)d_in[6];
    const float* lnvb  = (const float*)d_in[7];
    const float* Wq    = (const float*)d_in[8];
    const float* Wk    = (const float*)d_in[9];
    const float* bk    = (const float*)d_in[10];
    const float* Wv    = (const float*)d_in[11];
    const float* bv    = (const float*)d_in[12];
    const float* Woff  = (const float*)d_in[13];
    const float* boff  = (const float*)d_in[14];
    const float* Wout  = (const float*)d_in[15];
    const float* bout  = (const float*)d_in[16];

    bf16 *qlnh,*qlnl,*nh,*nl,*aoh,*aol;
    bf16 *wqTh,*wqTl,*wkvTh,*wkvTl,*wouth,*woutl;
    float *qb,*kvb,*biasq,*biaskv;
    cudaGetSymbolAddress((void**)&qlnh, g_qlnh);
    cudaGetSymbolAddress((void**)&qlnl, g_qlnl);
    cudaGetSymbolAddress((void**)&qb,   g_q);
    cudaGetSymbolAddress((void**)&nh,   g_nh);
    cudaGetSymbolAddress((void**)&nl,   g_nl);
    cudaGetSymbolAddress((void**)&kvb,  g_kv);
    cudaGetSymbolAddress((void**)&aoh,  g_aoh);
    cudaGetSymbolAddress((void**)&aol,  g_aol);
    cudaGetSymbolAddress((void**)&wqTh, g_wqTh);
    cudaGetSymbolAddress((void**)&wqTl, g_wqTl);
    cudaGetSymbolAddress((void**)&wkvTh, g_wkvTh);
    cudaGetSymbolAddress((void**)&wkvTl, g_wkvTl);
    cudaGetSymbolAddress((void**)&wouth, g_wouth);
    cudaGetSymbolAddress((void**)&woutl, g_woutl);
    cudaGetSymbolAddress((void**)&biasq,  g_biasq);
    cudaGetSymbolAddress((void**)&biaskv, g_biaskv);

    cudaFuncSetAttribute(bf16x3_gemm<1>, cudaFuncAttributeMaxDynamicSharedMemorySize, GEMM_SMEM);

    float* out_main = (float*)d_out;
    float* out_off  = out_main + (size_t)MQ * DIMc;

    // weight prep: gamma-folded transposed planes + beta-folded biases
    transpose_split_scale<<<dim3(INNERc/32, INNERc/32), dim3(32,8)>>>(Wq, lnqg, wqTh, wqTl, INNERc, INNERc);
    transpose_split_scale<<<dim3(INNERc/32, DIMc/32),   dim3(32,8)>>>(Wk, lnkg, wkvTh, wkvTl, DIMc, INNERc);
    transpose_split_scale<<<dim3(INNERc/32, DIMc/32),   dim3(32,8)>>>(Wv, lnvg,
        wkvTh + (size_t)INNERc*DIMc, wkvTl + (size_t)INNERc*DIMc, DIMc, INNERc);
    split_kernel<<<(DIMc*INNERc + 255)/256, 256>>>(Wout, wouth, woutl, DIMc*INNERc);
    fold_bias<<<INNERc, 32>>>(Wq, lnqb, nullptr, biasq, INNERc, INNERc);
    fold_bias<<<INNERc, 32>>>(Wk, lnkb, bk, biaskv, DIMc, INNERc);
    fold_bias<<<INNERc, 32>>>(Wv, lnvb, bv, biaskv + INNERc, DIMc, INNERc);

    lnq_kernel <<<MQ, 256>>>(x, px, qlnh, qlnl);
    lnkv_kernel<<<MKV, 256>>>(x, px, nh, nl);

    // q = nrm_q @ foldedWq + biasq
    bf16x3_gemm<1><<<dim3(INNERc/128, MQ/128),  256, GEMM_SMEM>>>(qlnh, qlnl, wqTh, wqTl, biasq, qb, INNERc, INNERc);
    // kv = nrm @ [foldedWk | foldedWv] + biaskv   (Ntot=1024)
    bf16x3_gemm<1><<<dim3(2*INNERc/128, MKV/128), 256, GEMM_SMEM>>>(nh, nl, wkvTh, wkvTl, biaskv, kvb, 2*INNERc, DIMc);

    off_kernel<<<MQ/128, 128>>>(qb, Woff, boff, out_off);
    attn_kernel<<<(MQ*Hh)/8, 256>>>(qb, kvb, out_off, aoh, aol);

    // out = ao @ Wout^T + bout
    bf16x3_gemm<1><<<dim3(DIMc/128, MQ/128), 256, GEMM_SMEM>>>(aoh, aol, wouth, woutl, bout, out_main, DIMc, INNERc);
}

// round 8
// speedup vs baseline: 1.3745x; 1.1104x over previous
#include <cuda_runtime.h>
#include <cuda_bf16.h>
#include <cstdint>
#include <math.h>

#define Bsz 4
#define Nn 4096
#define DIMc 256
#define Hh 8
#define DHd 64
#define Pp 2
#define INNERc 512
#define MQ (Bsz*Nn)      /* 16384 */
#define MKV (2*Bsz*Nn)   /* 32768 */

typedef __nv_bfloat16 bf16;

// ---------------- scratch (device globals) ----------------
__device__ bf16  g_qlnh[MQ * INNERc];
__device__ bf16  g_qlnl[MQ * INNERc];
__device__ float g_q   [MQ * INNERc];
__device__ bf16  g_nh  [MKV * DIMc];
__device__ bf16  g_nl  [MKV * DIMc];
__device__ float g_kv  [MKV * 2 * INNERc];
__device__ bf16  g_aoh [MQ * INNERc];
__device__ bf16  g_aol [MQ * INNERc];
__device__ bf16  g_wqTh[INNERc * INNERc];
__device__ bf16  g_wqTl[INNERc * INNERc];
__device__ bf16  g_wkvTh[2 * INNERc * DIMc];
__device__ bf16  g_wkvTl[2 * INNERc * DIMc];
__device__ bf16  g_wouth[DIMc * INNERc];
__device__ bf16  g_woutl[DIMc * INNERc];
__device__ float g_biasq [INNERc];
__device__ float g_biaskv[2 * INNERc];

// ================= helpers =================
__device__ __forceinline__ uint32_t smem_u32(const void* p){
    uint32_t a;
    asm("{ .reg .u64 t; cvta.to.shared.u64 t, %1; cvt.u32.u64 %0, t; }" : "=r"(a) : "l"(p));
    return a;
}
__device__ __forceinline__ void bsplit(float v, bf16& h, bf16& l){
    h = __float2bfloat16(v);
    l = __float2bfloat16(v - __bfloat162float(h));
}
__device__ __forceinline__ void mma_bf16(float d[4], const uint32_t a[4], const uint32_t b[2]){
    asm volatile("mma.sync.aligned.m16n8k16.row.col.f32.bf16.bf16.f32 "
        "{%0,%1,%2,%3}, {%4,%5,%6,%7}, {%8,%9}, {%0,%1,%2,%3};"
        : "+f"(d[0]),"+f"(d[1]),"+f"(d[2]),"+f"(d[3])
        : "r"(a[0]),"r"(a[1]),"r"(a[2]),"r"(a[3]),"r"(b[0]),"r"(b[1]));
}
__device__ __forceinline__ void ldsm4(uint32_t r[4], uint32_t addr){
    asm volatile("ldmatrix.sync.aligned.m8n8.x4.shared.b16 {%0,%1,%2,%3}, [%4];"
        : "=r"(r[0]),"=r"(r[1]),"=r"(r[2]),"=r"(r[3]) : "r"(addr));
}
__device__ __forceinline__ void cp16(uint32_t dst, const void* src){
    asm volatile("cp.async.cg.shared.global [%0], [%1], 16;" :: "r"(dst), "l"(src));
}
// swizzled byte offset within a plane: row (0..127) has 64B = 4 x 16B slots
__device__ __forceinline__ uint32_t swz(int r, int s){
    return (uint32_t)(r * 64 + ((s ^ ((r >> 1) & 3)) << 4));
}

// ================= bf16x3 tensor-core GEMM =================
// C[M,Ntot] = (Ah+Al)[M,K] @ (Bh+Bl)[Ntot,K]^T (+bias), x3 terms.
// 256 thr, tile 128x128, K-chunk 32, 3-stage cp.async (depth 2),
// swizzled 64B rows (32KB/stage), 2 CTAs/SM, one barrier per chunk.
#define TILE_B 8192
#define STAGE_B 32768
#define GEMM_SMEM (3*STAGE_B)

template<int HAS_BIAS>
__global__ void __launch_bounds__(256, 2)
bf16x3_gemm(const bf16* __restrict__ Ah, const bf16* __restrict__ Al,
            const bf16* __restrict__ Bh, const bf16* __restrict__ Bl,
            const float* __restrict__ bias, float* __restrict__ C,
            int Ntot, int K)
{
    extern __shared__ char smem[];
    const uint32_t sb = smem_u32(smem);
    const int tid = threadIdx.x, lane = tid & 31, wid = tid >> 5;
    const int wm = wid >> 2, wn = wid & 3;         // 2x4 warp grid, 64x32 per warp
    const int bm = blockIdx.y * 128, bn = blockIdx.x * 128;
    const int NC = K >> 5;

    const int lr  = tid >> 2;       // 0..63
    const int lcc = tid & 3;        // 16B slot within 32-k row segment
    const uint32_t w0 = swz(lr, lcc), w1 = swz(lr + 64, lcc);

    auto load_stage = [&](int buf, int kc){
        uint32_t base = sb + buf * STAGE_B;
        size_t ao = (size_t)(bm + lr) * K + kc + lcc * 8;
        size_t bo = (size_t)(bn + lr) * K + kc + lcc * 8;
        size_t row64 = (size_t)64 * K;
        cp16(base + w0,            Ah + ao);
        cp16(base + w1,            Ah + ao + row64);
        cp16(base + TILE_B + w0,   Al + ao);
        cp16(base + TILE_B + w1,   Al + ao + row64);
        cp16(base + 2*TILE_B + w0, Bh + bo);
        cp16(base + 2*TILE_B + w1, Bh + bo + row64);
        cp16(base + 3*TILE_B + w0, Bl + bo);
        cp16(base + 3*TILE_B + w1, Bl + bo + row64);
        asm volatile("cp.async.commit_group;" ::: "memory");
    };

    float acc[4][4][4] = {};

    auto compute = [&](int buf){
        uint32_t base = sb + buf * STAGE_B;
        #pragma unroll
        for (int ks = 0; ks < 2; ks++){
            const int slot = (lane >> 4) + ks * 2;
            uint32_t ah[4][4], al_[4][4];
            #pragma unroll
            for (int i = 0; i < 4; i++){
                int r = wm*64 + i*16 + (lane & 15);
                uint32_t a = base + swz(r, slot);
                ldsm4(ah[i],  a);
                ldsm4(al_[i], a + TILE_B);
            }
            #pragma unroll
            for (int jp = 0; jp < 2; jp++){
                int r = wn*32 + jp*16 + (lane & 15);
                uint32_t a = base + 2*TILE_B + swz(r, slot);
                uint32_t bh0[2], bh1[2], bl0[2], bl1[2], r4[4];
                ldsm4(r4, a);
                bh0[0]=r4[0]; bh1[0]=r4[1]; bh0[1]=r4[2]; bh1[1]=r4[3];
                ldsm4(r4, a + TILE_B);
                bl0[0]=r4[0]; bl1[0]=r4[1]; bl0[1]=r4[2]; bl1[1]=r4[3];
                #pragma unroll
                for (int i = 0; i < 4; i++){
                    mma_bf16(acc[i][jp*2],   ah[i],  bh0);
                    mma_bf16(acc[i][jp*2],   ah[i],  bl0);
                    mma_bf16(acc[i][jp*2],   al_[i], bh0);
                    mma_bf16(acc[i][jp*2+1], ah[i],  bh1);
                    mma_bf16(acc[i][jp*2+1], ah[i],  bl1);
                    mma_bf16(acc[i][jp*2+1], al_[i], bh1);
                }
            }
        }
    };

    load_stage(0, 0);
    load_stage(1, 32);

    for (int c = 0; c < NC; c++){
        if (c < NC - 1) asm volatile("cp.async.wait_group 1;" ::: "memory");
        else            asm volatile("cp.async.wait_group 0;" ::: "memory");
        __syncthreads();
        if (c + 2 < NC) load_stage((c + 2) % 3, (c + 2) * 32);
        compute(c % 3);
    }

    #pragma unroll
    for (int i = 0; i < 4; i++){
        int r0 = bm + wm*64 + i*16 + (lane >> 2);
        #pragma unroll
        for (int j = 0; j < 4; j++){
            int c0 = bn + wn*32 + j*8 + (lane & 3)*2;
            float b0 = 0.f, b1 = 0.f;
            if (HAS_BIAS){ b0 = bias[c0]; b1 = bias[c0+1]; }
            *(float2*)(C + (size_t)r0 * Ntot + c0)     = make_float2(acc[i][j][0]+b0, acc[i][j][1]+b1);
            *(float2*)(C + (size_t)(r0+8) * Ntot + c0) = make_float2(acc[i][j][2]+b0, acc[i][j][3]+b1);
        }
    }
}

// ================= merged weight prep (single launch) =================
// blocks [0,256)    : transpose+scale+split Wq   (grid 16x16)
// blocks [256,384)  : transpose+scale+split Wk   (grid 16x8)
// blocks [384,512)  : transpose+scale+split Wv   (grid 16x8)
// blocks [512,1024) : elementwise split Wout
// blocks [1024,1088): fold bias q   (8 cols per block, warp each)
// blocks [1088,1152): fold bias k
// blocks [1152,1216): fold bias v
__device__ __forceinline__ void tss_body(const float* in, const float* g,
                                         bf16* oh, bf16* ol, int R, int C,
                                         int bx, int by, int tx, int ty){
    __shared__ float tile[32][33];
    int c0 = bx * 32, r0 = by * 32;
    #pragma unroll
    for (int i = 0; i < 32; i += 8){
        int r = r0 + ty + i;
        tile[ty + i][tx] = in[(size_t)r * C + c0 + tx] * g[r];
    }
    __syncthreads();
    #pragma unroll
    for (int i = 0; i < 32; i += 8){
        float v = tile[tx][ty + i];
        bf16 h, l; bsplit(v, h, l);
        size_t o = (size_t)(c0 + ty + i) * R + r0 + tx;
        oh[o] = h; ol[o] = l;
    }
}
__device__ __forceinline__ void fold_body(const float* W, const float* beta,
                                          const float* base, float* out,
                                          int K, int N, int n, int lane){
    float s = 0.f;
    for (int k = lane; k < K; k += 32) s += beta[k] * W[(size_t)k * N + n];
    #pragma unroll
    for (int o = 16; o > 0; o >>= 1) s += __shfl_xor_sync(0xffffffffu, s, o);
    if (lane == 0) out[n] = s + (base ? base[n] : 0.f);
}

__global__ void prep_kernel(const float* __restrict__ Wq, const float* __restrict__ lnqg, const float* __restrict__ lnqb,
                            const float* __restrict__ Wk, const float* __restrict__ lnkg, const float* __restrict__ lnkb, const float* __restrict__ bk,
                            const float* __restrict__ Wv, const float* __restrict__ lnvg, const float* __restrict__ lnvb, const float* __restrict__ bv,
                            const float* __restrict__ Wout,
                            bf16* __restrict__ wqTh, bf16* __restrict__ wqTl,
                            bf16* __restrict__ wkvTh, bf16* __restrict__ wkvTl,
                            bf16* __restrict__ wouth, bf16* __restrict__ woutl,
                            float* __restrict__ biasq, float* __restrict__ biaskv){
    int id = blockIdx.x;
    int tx = threadIdx.x, ty = threadIdx.y;           // (32, 8)
    if (id < 256){
        tss_body(Wq, lnqg, wqTh, wqTl, INNERc, INNERc, id & 15, id >> 4, tx, ty);
    } else if (id < 384){
        int l = id - 256;
        tss_body(Wk, lnkg, wkvTh, wkvTl, DIMc, INNERc, l & 15, l >> 4, tx, ty);
    } else if (id < 512){
        int l = id - 384;
        tss_body(Wv, lnvg, wkvTh + (size_t)INNERc*DIMc, wkvTl + (size_t)INNERc*DIMc,
                 DIMc, INNERc, l & 15, l >> 4, tx, ty);
    } else if (id < 1024){
        int i = (id - 512) * 256 + ty * 32 + tx;
        bf16 h, l; bsplit(Wout[i], h, l);
        wouth[i] = h; woutl[i] = l;
    } else if (id < 1088){
        int n = (id - 1024) * 8 + ty;
        fold_body(Wq, lnqb, nullptr, biasq, INNERc, INNERc, n, tx);
    } else if (id < 1152){
        int n = (id - 1088) * 8 + ty;
        fold_body(Wk, lnkb, bk, biaskv, DIMc, INNERc, n, tx);
    } else {
        int n = (id - 1152) * 8 + ty;
        fold_body(Wv, lnvb, bv, biaskv + INNERc, DIMc, INNERc, n, tx);
    }
}

// ================= block reduce =================
__device__ __forceinline__ float2 blockReduce2(float a, float b) {
    __shared__ float2 sbuf[8];
    #pragma unroll
    for (int o = 16; o > 0; o >>= 1) {
        a += __shfl_xor_sync(0xffffffffu, a, o);
        b += __shfl_xor_sync(0xffffffffu, b, o);
    }
    int w = threadIdx.x >> 5;
    if ((threadIdx.x & 31) == 0) sbuf[w] = make_float2(a, b);
    __syncthreads();
    if (w == 0) {
        int nw = blockDim.x >> 5;
        float2 r = (threadIdx.x < nw) ? sbuf[threadIdx.x] : make_float2(0.f, 0.f);
        #pragma unroll
        for (int o = 4; o > 0; o >>= 1) {
            r.x += __shfl_xor_sync(0xffffffffu, r.x, o);
            r.y += __shfl_xor_sync(0xffffffffu, r.y, o);
        }
        if (threadIdx.x == 0) sbuf[0] = r;
    }
    __syncthreads();
    return sbuf[0];
}

// ============ LN over concat (512) ============
__global__ void lnq_kernel(const float* __restrict__ x, const float* __restrict__ px,
                           bf16* __restrict__ oh, bf16* __restrict__ ol) {
    int row = blockIdx.x;
    int t = threadIdx.x;
    float v0 = x [row * DIMc + t];
    float v1 = px[row * DIMc + t];
    float2 r = blockReduce2(v0 + v1, v0 * v0 + v1 * v1);
    float mean = r.x * (1.0f / 512.0f);
    float var  = r.y * (1.0f / 512.0f) - mean * mean;
    float rstd = rsqrtf(var + 1e-5f);
    bf16 h, l;
    bsplit((v0 - mean) * rstd, h, l); oh[row * INNERc + t] = h;       ol[row * INNERc + t] = l;
    bsplit((v1 - mean) * rstd, h, l); oh[row * INNERc + 256 + t] = h; ol[row * INNERc + 256 + t] = l;
}

// ============ LN over kv (256) ============
__global__ void lnkv_kernel(const float* __restrict__ x, const float* __restrict__ px,
                            bf16* __restrict__ nh, bf16* __restrict__ nl) {
    int row = blockIdx.x;
    int t = threadIdx.x;
    const float* src = (row < Bsz * Nn) ? x : px;
    int r2 = (row < Bsz * Nn) ? row : row - Bsz * Nn;
    float v = src[r2 * DIMc + t];
    float2 r = blockReduce2(v, v * v);
    float mean = r.x * (1.0f / 256.0f);
    float var  = r.y * (1.0f / 256.0f) - mean * mean;
    float rstd = rsqrtf(var + 1e-5f);
    bf16 h, l;
    bsplit((v - mean) * rstd, h, l);
    nh[row * DIMc + t] = h; nl[row * DIMc + t] = l;
}

// ============ offsets projection (fp32) — writes transposed (B,H,P,N) ============
__global__ void off_kernel(const float* __restrict__ q, const float* __restrict__ Woff,
                           const float* __restrict__ boff, float* __restrict__ off_out) {
    __shared__ float w[16][INNERc];
    int tid = threadIdx.x;
    for (int i = tid; i < 16 * INNERc; i += 128) w[i >> 9][i & 511] = Woff[i];
    __syncthreads();
    int m = blockIdx.x * 128 + tid;        // b*N + n
    const float* qr = q + (size_t)m * INNERc;
    float acc[16];
    #pragma unroll
    for (int j = 0; j < 16; j++) acc[j] = boff[j];
    for (int k0 = 0; k0 < INNERc; k0 += 4){
        float4 qv = *(const float4*)(qr + k0);
        #pragma unroll
        for (int j = 0; j < 16; j++)
            acc[j] += qv.x * w[j][k0] + qv.y * w[j][k0+1] + qv.z * w[j][k0+2] + qv.w * w[j][k0+3];
    }
    int b = m >> 12, n = m & 4095;
    #pragma unroll
    for (int j = 0; j < 16; j++)
        off_out[((size_t)(b * 16 + j)) * Nn + n] = acc[j];
}

// ================= attention (fused KV layout [row,1024]) =================
__global__ void attn_kernel(const float* __restrict__ q, const float* __restrict__ kv,
                            const float* __restrict__ off_t,
                            bf16* __restrict__ aoh, bf16* __restrict__ aol) {
    int gw = (blockIdx.x * blockDim.x + threadIdx.x) >> 5;
    int lane = threadIdx.x & 31;
    if (gw >= MQ * Hh) return;
    int bn = gw / Hh;
    int h  = gw - bn * Hh;
    int b  = bn / Nn;
    int n  = bn - b * Nn;

    float o0 = off_t[((size_t)(b * 16 + h * Pp + 0)) * Nn + n];
    float o1 = off_t[((size_t)(b * 16 + h * Pp + 1)) * Nn + n];
    float t0 = fminf(fmaxf((float)n + o0, 0.f), (float)(2 * Nn - 1));
    float t1 = fminf(fmaxf((float)n + o1, 0.f), (float)(2 * Nn - 1));
    int j0 = (int)t0, j1 = (int)t1;
    int s0 = (j0 >= Nn) ? 1 : 0; int np0 = j0 - s0 * Nn;
    int s1 = (j1 >= Nn) ? 1 : 0; int np1 = j1 - s1 * Nn;

    const float* qb  = q + (size_t)bn * INNERc + h * DHd;
    const float* r0p = kv + ((size_t)(s0 * Bsz + b) * Nn + np0) * (2*INNERc) + h * DHd;
    const float* r1p = kv + ((size_t)(s1 * Bsz + b) * Nn + np1) * (2*INNERc) + h * DHd;

    float qa = qb[lane], qc = qb[lane + 32];
    float d0 = qa * r0p[lane] + qc * r0p[lane + 32];
    float d1 = qa * r1p[lane] + qc * r1p[lane + 32];
    #pragma unroll
    for (int o = 16; o > 0; o >>= 1) {
        d0 += __shfl_xor_sync(0xffffffffu, d0, o);
        d1 += __shfl_xor_sync(0xffffffffu, d1, o);
    }
    const float scale = 0.125f;
    d0 *= scale; d1 *= scale;
    float mx = fmaxf(d0, d1);
    float e0 = __expf(d0 - mx), e1 = __expf(d1 - mx);
    float inv = 1.0f / (e0 + e1);
    float a0 = e0 * inv, a1 = e1 * inv;

    const float* v0p = r0p + INNERc;
    const float* v1p = r1p + INNERc;
    float r0 = a0 * v0p[lane]      + a1 * v1p[lane];
    float r1 = a0 * v0p[lane + 32] + a1 * v1p[lane + 32];
    bf16 hh, ll;
    size_t o_base = (size_t)bn * INNERc + h * DHd;
    bsplit(r0, hh, ll); aoh[o_base + lane]      = hh; aol[o_base + lane]      = ll;
    bsplit(r1, hh, ll); aoh[o_base + lane + 32] = hh; aol[o_base + lane + 32] = ll;
}

// ================= launch =================
extern "C" void kernel_launch(void* const* d_in, const int* in_sizes, int n_in,
                              void* d_out, int out_size) {
    const float* x     = (const float*)d_in[0];
    const float* px    = (const float*)d_in[1];
    const float* lnqg  = (const float*)d_in[2];
    const float* lnqb  = (const float*)d_in[3];
    const float* lnkg  = (const float*)d_in[4];
    const float* lnkb  = (const float*)d_in[5];
    const float* lnvg  = (const float*)d_in[6];
    const float* lnvb  = (const float*)d_in[7];
    const float* Wq    = (const float*)d_in[8];
    const float* Wk    = (const float*)d_in[9];
    const float* bk    = (const float*)d_in[10];
    const float* Wv    = (const float*)d_in[11];
    const float* bv    = (const float*)d_in[12];
    const float* Woff  = (const float*)d_in[13];
    const float* boff  = (const float*)d_in[14];
    const float* Wout  = (const float*)d_in[15];
    const float* bout  = (const float*)d_in[16];

    bf16 *qlnh,*qlnl,*nh,*nl,*aoh,*aol;
    bf16 *wqTh,*wqTl,*wkvTh,*wkvTl,*wouth,*woutl;
    float *qb,*kvb,*biasq,*biaskv;
    cudaGetSymbolAddress((void**)&qlnh, g_qlnh);
    cudaGetSymbolAddress((void**)&qlnl, g_qlnl);
    cudaGetSymbolAddress((void**)&qb,   g_q);
    cudaGetSymbolAddress((void**)&nh,   g_nh);
    cudaGetSymbolAddress((void**)&nl,   g_nl);
    cudaGetSymbolAddress((void**)&kvb,  g_kv);
    cudaGetSymbolAddress((void**)&aoh,  g_aoh);
    cudaGetSymbolAddress((void**)&aol,  g_aol);
    cudaGetSymbolAddress((void**)&wqTh, g_wqTh);
    cudaGetSymbolAddress((void**)&wqTl, g_wqTl);
    cudaGetSymbolAddress((void**)&wkvTh, g_wkvTh);
    cudaGetSymbolAddress((void**)&wkvTl, g_wkvTl);
    cudaGetSymbolAddress((void**)&wouth, g_wouth);
    cudaGetSymbolAddress((void**)&woutl, g_woutl);
    cudaGetSymbolAddress((void**)&biasq,  g_biasq);
    cudaGetSymbolAddress((void**)&biaskv, g_biaskv);

    cudaFuncSetAttribute(bf16x3_gemm<1>, cudaFuncAttributeMaxDynamicSharedMemorySize, GEMM_SMEM);

    float* out_main = (float*)d_out;
    float* out_off  = out_main + (size_t)MQ * DIMc;

    // 0: all weight prep in one launch
    prep_kernel<<<1216, dim3(32,8)>>>(Wq, lnqg, lnqb, Wk, lnkg, lnkb, bk,
                                      Wv, lnvg, lnvb, bv, Wout,
                                      wqTh, wqTl, wkvTh, wkvTl, wouth, woutl,
                                      biasq, biaskv);
    // 1,2: layernorms
    lnq_kernel <<<MQ, 256>>>(x, px, qlnh, qlnl);
    lnkv_kernel<<<MKV, 256>>>(x, px, nh, nl);

    // 3: kv = nrm @ [foldedWk | foldedWv] + biaskv  (profiled launch)
    bf16x3_gemm<1><<<dim3(2*INNERc/128, MKV/128), 256, GEMM_SMEM>>>(nh, nl, wkvTh, wkvTl, biaskv, kvb, 2*INNERc, DIMc);
    // 4: q = nrm_q @ foldedWq + biasq
    bf16x3_gemm<1><<<dim3(INNERc/128, MQ/128),  256, GEMM_SMEM>>>(qlnh, qlnl, wqTh, wqTl, biasq, qb, INNERc, INNERc);

    // 5,6: offsets + attention
    off_kernel<<<MQ/128, 128>>>(qb, Woff, boff, out_off);
    attn_kernel<<<(MQ*Hh)/8, 256>>>(qb, kvb, out_off, aoh, aol);

    // 7: out = ao @ Wout^T + bout
    bf16x3_gemm<1><<<dim3(DIMc/128, MQ/128), 256, GEMM_SMEM>>>(aoh, aol, wouth, woutl, bout, out_main, DIMc, INNERc);
}

// round 9
// speedup vs baseline: 1.4031x; 1.0208x over previous
#include <cuda_runtime.h>
#include <cuda_bf16.h>
#include <cstdint>
#include <math.h>

#define Bsz 4
#define Nn 4096
#define DIMc 256
#define Hh 8
#define DHd 64
#define Pp 2
#define INNERc 512
#define MQ (Bsz*Nn)      /* 16384 */
#define MKV (2*Bsz*Nn)   /* 32768 */

typedef __nv_bfloat16 bf16;

// ---------------- scratch (device globals) ----------------
__device__ bf16  g_qlnh[MQ * INNERc];
__device__ bf16  g_qlnl[MQ * INNERc];
__device__ float g_q   [MQ * INNERc];
__device__ bf16  g_nh  [MKV * DIMc];
__device__ bf16  g_nl  [MKV * DIMc];
__device__ float g_kv  [MKV * 2 * INNERc];
__device__ bf16  g_aoh [MQ * INNERc];
__device__ bf16  g_aol [MQ * INNERc];
__device__ bf16  g_wqTh[INNERc * INNERc];
__device__ bf16  g_wqTl[INNERc * INNERc];
__device__ bf16  g_wkvTh[2 * INNERc * DIMc];
__device__ bf16  g_wkvTl[2 * INNERc * DIMc];
__device__ bf16  g_wouth[DIMc * INNERc];
__device__ bf16  g_woutl[DIMc * INNERc];
__device__ float g_biasq [INNERc];
__device__ float g_biaskv[2 * INNERc];

// ================= helpers =================
__device__ __forceinline__ uint32_t smem_u32(const void* p){
    uint32_t a;
    asm("{ .reg .u64 t; cvta.to.shared.u64 t, %1; cvt.u32.u64 %0, t; }" : "=r"(a) : "l"(p));
    return a;
}
__device__ __forceinline__ void bsplit(float v, bf16& h, bf16& l){
    h = __float2bfloat16(v);
    l = __float2bfloat16(v - __bfloat162float(h));
}
__device__ __forceinline__ void mma_bf16(float d[4], const uint32_t a[4], const uint32_t b[2]){
    asm volatile("mma.sync.aligned.m16n8k16.row.col.f32.bf16.bf16.f32 "
        "{%0,%1,%2,%3}, {%4,%5,%6,%7}, {%8,%9}, {%0,%1,%2,%3};"
        : "+f"(d[0]),"+f"(d[1]),"+f"(d[2]),"+f"(d[3])
        : "r"(a[0]),"r"(a[1]),"r"(a[2]),"r"(a[3]),"r"(b[0]),"r"(b[1]));
}
__device__ __forceinline__ void ldsm4(uint32_t r[4], uint32_t addr){
    asm volatile("ldmatrix.sync.aligned.m8n8.x4.shared.b16 {%0,%1,%2,%3}, [%4];"
        : "=r"(r[0]),"=r"(r[1]),"=r"(r[2]),"=r"(r[3]) : "r"(addr));
}
__device__ __forceinline__ void cp16(uint32_t dst, const void* src){
    asm volatile("cp.async.cg.shared.global [%0], [%1], 16;" :: "r"(dst), "l"(src));
}
// swizzled byte offset within a plane: row (0..127) has 64B = 4 x 16B slots
__device__ __forceinline__ uint32_t swz(int r, int s){
    return (uint32_t)(r * 64 + ((s ^ ((r >> 1) & 3)) << 4));
}

// ================= bf16x3 tensor-core GEMM =================
// C[M,Ntot] = (Ah+Al)[M,K] @ (Bh+Bl)[Ntot,K]^T (+bias), x3 terms.
// 256 thr, tile 128x128, K-chunk 32, 3-stage cp.async (depth 2),
// swizzled 64B rows, 2 CTAs/SM, hoisted ldsm addresses, term-major mma.
#define TILE_B 8192
#define STAGE_B 32768
#define GEMM_SMEM (3*STAGE_B)

template<int HAS_BIAS>
__global__ void __launch_bounds__(256, 2)
bf16x3_gemm(const bf16* __restrict__ Ah, const bf16* __restrict__ Al,
            const bf16* __restrict__ Bh, const bf16* __restrict__ Bl,
            const float* __restrict__ bias, float* __restrict__ C,
            int Ntot, int K)
{
    extern __shared__ char smem[];
    const uint32_t sb = smem_u32(smem);
    const int tid = threadIdx.x, lane = tid & 31, wid = tid >> 5;
    const int wm = wid >> 2, wn = wid & 3;         // 2x4 warp grid, 64x32 per warp
    const int bm = blockIdx.y * 128, bn = blockIdx.x * 128;
    const int NC = K >> 5;

    const int lr  = tid >> 2;       // 0..63
    const int lcc = tid & 3;        // 16B slot within 32-k row segment
    const uint32_t w0 = swz(lr, lcc), w1 = swz(lr + 64, lcc);

    // hoisted stage-relative ldsm offsets (chunk-invariant)
    uint32_t aoff[2][4], boff[2][2];
    #pragma unroll
    for (int ks = 0; ks < 2; ks++){
        const int slot = (lane >> 4) + ks * 2;
        #pragma unroll
        for (int i = 0; i < 4; i++)
            aoff[ks][i] = swz(wm*64 + i*16 + (lane & 15), slot);
        #pragma unroll
        for (int jp = 0; jp < 2; jp++)
            boff[ks][jp] = 2*TILE_B + swz(wn*32 + jp*16 + (lane & 15), slot);
    }

    auto load_stage = [&](int buf, int kc){
        uint32_t base = sb + buf * STAGE_B;
        size_t ao = (size_t)(bm + lr) * K + kc + lcc * 8;
        size_t bo = (size_t)(bn + lr) * K + kc + lcc * 8;
        size_t row64 = (size_t)64 * K;
        cp16(base + w0,            Ah + ao);
        cp16(base + w1,            Ah + ao + row64);
        cp16(base + TILE_B + w0,   Al + ao);
        cp16(base + TILE_B + w1,   Al + ao + row64);
        cp16(base + 2*TILE_B + w0, Bh + bo);
        cp16(base + 2*TILE_B + w1, Bh + bo + row64);
        cp16(base + 3*TILE_B + w0, Bl + bo);
        cp16(base + 3*TILE_B + w1, Bl + bo + row64);
        asm volatile("cp.async.commit_group;" ::: "memory");
    };

    float acc[4][4][4] = {};

    auto compute = [&](int buf){
        uint32_t base = sb + buf * STAGE_B;
        #pragma unroll
        for (int ks = 0; ks < 2; ks++){
            uint32_t BH[4][2], BL[4][2];
            #pragma unroll
            for (int jp = 0; jp < 2; jp++){
                uint32_t a = base + boff[ks][jp];
                uint32_t r4[4];
                ldsm4(r4, a);
                BH[jp*2][0]=r4[0]; BH[jp*2+1][0]=r4[1]; BH[jp*2][1]=r4[2]; BH[jp*2+1][1]=r4[3];
                ldsm4(r4, a + TILE_B);
                BL[jp*2][0]=r4[0]; BL[jp*2+1][0]=r4[1]; BL[jp*2][1]=r4[2]; BL[jp*2+1][1]=r4[3];
            }
            #pragma unroll
            for (int i = 0; i < 4; i++){
                uint32_t a = base + aoff[ks][i];
                uint32_t ah[4], al_[4];
                ldsm4(ah,  a);
                ldsm4(al_, a + TILE_B);
                #pragma unroll
                for (int j = 0; j < 4; j++) mma_bf16(acc[i][j], ah,  BH[j]);
                #pragma unroll
                for (int j = 0; j < 4; j++) mma_bf16(acc[i][j], ah,  BL[j]);
                #pragma unroll
                for (int j = 0; j < 4; j++) mma_bf16(acc[i][j], al_, BH[j]);
            }
        }
    };

    load_stage(0, 0);
    load_stage(1, 32);

    for (int c = 0; c < NC; c++){
        if (c < NC - 1) asm volatile("cp.async.wait_group 1;" ::: "memory");
        else            asm volatile("cp.async.wait_group 0;" ::: "memory");
        __syncthreads();
        if (c + 2 < NC) load_stage((c + 2) % 3, (c + 2) * 32);
        compute(c % 3);
    }

    #pragma unroll
    for (int i = 0; i < 4; i++){
        int r0 = bm + wm*64 + i*16 + (lane >> 2);
        #pragma unroll
        for (int j = 0; j < 4; j++){
            int c0 = bn + wn*32 + j*8 + (lane & 3)*2;
            float b0 = 0.f, b1 = 0.f;
            if (HAS_BIAS){ b0 = bias[c0]; b1 = bias[c0+1]; }
            *(float2*)(C + (size_t)r0 * Ntot + c0)     = make_float2(acc[i][j][0]+b0, acc[i][j][1]+b1);
            *(float2*)(C + (size_t)(r0+8) * Ntot + c0) = make_float2(acc[i][j][2]+b0, acc[i][j][3]+b1);
        }
    }
}

// ================= merged weight prep (single launch) =================
__device__ __forceinline__ void tss_body(const float* in, const float* g,
                                         bf16* oh, bf16* ol, int R, int C,
                                         int bx, int by, int tx, int ty){
    __shared__ float tile[32][33];
    int c0 = bx * 32, r0 = by * 32;
    #pragma unroll
    for (int i = 0; i < 32; i += 8){
        int r = r0 + ty + i;
        tile[ty + i][tx] = in[(size_t)r * C + c0 + tx] * g[r];
    }
    __syncthreads();
    #pragma unroll
    for (int i = 0; i < 32; i += 8){
        float v = tile[tx][ty + i];
        bf16 h, l; bsplit(v, h, l);
        size_t o = (size_t)(c0 + ty + i) * R + r0 + tx;
        oh[o] = h; ol[o] = l;
    }
}
__device__ __forceinline__ void fold_body(const float* W, const float* beta,
                                          const float* base, float* out,
                                          int K, int N, int n, int lane){
    float s = 0.f;
    for (int k = lane; k < K; k += 32) s += beta[k] * W[(size_t)k * N + n];
    #pragma unroll
    for (int o = 16; o > 0; o >>= 1) s += __shfl_xor_sync(0xffffffffu, s, o);
    if (lane == 0) out[n] = s + (base ? base[n] : 0.f);
}

__global__ void prep_kernel(const float* __restrict__ Wq, const float* __restrict__ lnqg, const float* __restrict__ lnqb,
                            const float* __restrict__ Wk, const float* __restrict__ lnkg, const float* __restrict__ lnkb, const float* __restrict__ bk,
                            const float* __restrict__ Wv, const float* __restrict__ lnvg, const float* __restrict__ lnvb, const float* __restrict__ bv,
                            const float* __restrict__ Wout,
                            bf16* __restrict__ wqTh, bf16* __restrict__ wqTl,
                            bf16* __restrict__ wkvTh, bf16* __restrict__ wkvTl,
                            bf16* __restrict__ wouth, bf16* __restrict__ woutl,
                            float* __restrict__ biasq, float* __restrict__ biaskv){
    int id = blockIdx.x;
    int tx = threadIdx.x, ty = threadIdx.y;           // (32, 8)
    if (id < 256){
        tss_body(Wq, lnqg, wqTh, wqTl, INNERc, INNERc, id & 15, id >> 4, tx, ty);
    } else if (id < 384){
        int l = id - 256;
        tss_body(Wk, lnkg, wkvTh, wkvTl, DIMc, INNERc, l & 15, l >> 4, tx, ty);
    } else if (id < 512){
        int l = id - 384;
        tss_body(Wv, lnvg, wkvTh + (size_t)INNERc*DIMc, wkvTl + (size_t)INNERc*DIMc,
                 DIMc, INNERc, l & 15, l >> 4, tx, ty);
    } else if (id < 1024){
        int i = (id - 512) * 256 + ty * 32 + tx;
        bf16 h, l; bsplit(Wout[i], h, l);
        wouth[i] = h; woutl[i] = l;
    } else if (id < 1088){
        int n = (id - 1024) * 8 + ty;
        fold_body(Wq, lnqb, nullptr, biasq, INNERc, INNERc, n, tx);
    } else if (id < 1152){
        int n = (id - 1088) * 8 + ty;
        fold_body(Wk, lnkb, bk, biaskv, DIMc, INNERc, n, tx);
    } else {
        int n = (id - 1152) * 8 + ty;
        fold_body(Wv, lnvb, bv, biaskv + INNERc, DIMc, INNERc, n, tx);
    }
}

// ================= block reduce =================
__device__ __forceinline__ float2 blockReduce2(float a, float b) {
    __shared__ float2 sbuf[8];
    #pragma unroll
    for (int o = 16; o > 0; o >>= 1) {
        a += __shfl_xor_sync(0xffffffffu, a, o);
        b += __shfl_xor_sync(0xffffffffu, b, o);
    }
    int w = threadIdx.x >> 5;
    if ((threadIdx.x & 31) == 0) sbuf[w] = make_float2(a, b);
    __syncthreads();
    if (w == 0) {
        int nw = blockDim.x >> 5;
        float2 r = (threadIdx.x < nw) ? sbuf[threadIdx.x] : make_float2(0.f, 0.f);
        #pragma unroll
        for (int o = 4; o > 0; o >>= 1) {
            r.x += __shfl_xor_sync(0xffffffffu, r.x, o);
            r.y += __shfl_xor_sync(0xffffffffu, r.y, o);
        }
        if (threadIdx.x == 0) sbuf[0] = r;
    }
    __syncthreads();
    return sbuf[0];
}

// ============ LN over concat (512) ============
__global__ void lnq_kernel(const float* __restrict__ x, const float* __restrict__ px,
                           bf16* __restrict__ oh, bf16* __restrict__ ol) {
    int row = blockIdx.x;
    int t = threadIdx.x;
    float v0 = x [row * DIMc + t];
    float v1 = px[row * DIMc + t];
    float2 r = blockReduce2(v0 + v1, v0 * v0 + v1 * v1);
    float mean = r.x * (1.0f / 512.0f);
    float var  = r.y * (1.0f / 512.0f) - mean * mean;
    float rstd = rsqrtf(var + 1e-5f);
    bf16 h, l;
    bsplit((v0 - mean) * rstd, h, l); oh[row * INNERc + t] = h;       ol[row * INNERc + t] = l;
    bsplit((v1 - mean) * rstd, h, l); oh[row * INNERc + 256 + t] = h; ol[row * INNERc + 256 + t] = l;
}

// ============ LN over kv (256) ============
__global__ void lnkv_kernel(const float* __restrict__ x, const float* __restrict__ px,
                            bf16* __restrict__ nh, bf16* __restrict__ nl) {
    int row = blockIdx.x;
    int t = threadIdx.x;
    const float* src = (row < Bsz * Nn) ? x : px;
    int r2 = (row < Bsz * Nn) ? row : row - Bsz * Nn;
    float v = src[r2 * DIMc + t];
    float2 r = blockReduce2(v, v * v);
    float mean = r.x * (1.0f / 256.0f);
    float var  = r.y * (1.0f / 256.0f) - mean * mean;
    float rstd = rsqrtf(var + 1e-5f);
    bf16 h, l;
    bsplit((v - mean) * rstd, h, l);
    nh[row * DIMc + t] = h; nl[row * DIMc + t] = l;
}

// ============ offsets projection (fp32) — writes transposed (B,H,P,N) ============
__global__ void off_kernel(const float* __restrict__ q, const float* __restrict__ Woff,
                           const float* __restrict__ boff, float* __restrict__ off_out) {
    __shared__ float w[16][INNERc];
    int tid = threadIdx.x;
    for (int i = tid; i < 16 * INNERc; i += 128) w[i >> 9][i & 511] = Woff[i];
    __syncthreads();
    int m = blockIdx.x * 128 + tid;        // b*N + n
    const float* qr = q + (size_t)m * INNERc;
    float acc[16];
    #pragma unroll
    for (int j = 0; j < 16; j++) acc[j] = boff[j];
    for (int k0 = 0; k0 < INNERc; k0 += 4){
        float4 qv = *(const float4*)(qr + k0);
        #pragma unroll
        for (int j = 0; j < 16; j++)
            acc[j] += qv.x * w[j][k0] + qv.y * w[j][k0+1] + qv.z * w[j][k0+2] + qv.w * w[j][k0+3];
    }
    int b = m >> 12, n = m & 4095;
    #pragma unroll
    for (int j = 0; j < 16; j++)
        off_out[((size_t)(b * 16 + j)) * Nn + n] = acc[j];
}

// ================= attention (fused KV layout [row,1024]) =================
__global__ void attn_kernel(const float* __restrict__ q, const float* __restrict__ kv,
                            const float* __restrict__ off_t,
                            bf16* __restrict__ aoh, bf16* __restrict__ aol) {
    int gw = (blockIdx.x * blockDim.x + threadIdx.x) >> 5;
    int lane = threadIdx.x & 31;
    if (gw >= MQ * Hh) return;
    int bn = gw / Hh;
    int h  = gw - bn * Hh;
    int b  = bn / Nn;
    int n  = bn - b * Nn;

    float o0 = off_t[((size_t)(b * 16 + h * Pp + 0)) * Nn + n];
    float o1 = off_t[((size_t)(b * 16 + h * Pp + 1)) * Nn + n];
    float t0 = fminf(fmaxf((float)n + o0, 0.f), (float)(2 * Nn - 1));
    float t1 = fminf(fmaxf((float)n + o1, 0.f), (float)(2 * Nn - 1));
    int j0 = (int)t0, j1 = (int)t1;
    int s0 = (j0 >= Nn) ? 1 : 0; int np0 = j0 - s0 * Nn;
    int s1 = (j1 >= Nn) ? 1 : 0; int np1 = j1 - s1 * Nn;

    const float* qb  = q + (size_t)bn * INNERc + h * DHd;
    const float* r0p = kv + ((size_t)(s0 * Bsz + b) * Nn + np0) * (2*INNERc) + h * DHd;
    const float* r1p = kv + ((size_t)(s1 * Bsz + b) * Nn + np1) * (2*INNERc) + h * DHd;

    float qa = qb[lane], qc = qb[lane + 32];
    float d0 = qa * r0p[lane] + qc * r0p[lane + 32];
    float d1 = qa * r1p[lane] + qc * r1p[lane + 32];
    #pragma unroll
    for (int o = 16; o > 0; o >>= 1) {
        d0 += __shfl_xor_sync(0xffffffffu, d0, o);
        d1 += __shfl_xor_sync(0xffffffffu, d1, o);
    }
    const float scale = 0.125f;
    d0 *= scale; d1 *= scale;
    float mx = fmaxf(d0, d1);
    float e0 = __expf(d0 - mx), e1 = __expf(d1 - mx);
    float inv = 1.0f / (e0 + e1);
    float a0 = e0 * inv, a1 = e1 * inv;

    const float* v0p = r0p + INNERc;
    const float* v1p = r1p + INNERc;
    float r0 = a0 * v0p[lane]      + a1 * v1p[lane];
    float r1 = a0 * v0p[lane + 32] + a1 * v1p[lane + 32];
    bf16 hh, ll;
    size_t o_base = (size_t)bn * INNERc + h * DHd;
    bsplit(r0, hh, ll); aoh[o_base + lane]      = hh; aol[o_base + lane]      = ll;
    bsplit(r1, hh, ll); aoh[o_base + lane + 32] = hh; aol[o_base + lane + 32] = ll;
}

// ================= launch =================
extern "C" void kernel_launch(void* const* d_in, const int* in_sizes, int n_in,
                              void* d_out, int out_size) {
    const float* x     = (const float*)d_in[0];
    const float* px    = (const float*)d_in[1];
    const float* lnqg  = (const float*)d_in[2];
    const float* lnqb  = (const float*)d_in[3];
    const float* lnkg  = (const float*)d_in[4];
    const float* lnkb  = (const float*)d_in[5];
    const float* lnvg  = (const float*)d_in[6];
    const float* lnvb  = (const float*)d_in[7];
    const float* Wq    = (const float*)d_in[8];
    const float* Wk    = (const float*)d_in[9];
    const float* bk    = (const float*)d_in[10];
    const float* Wv    = (const float*)d_in[11];
    const float* bv    = (const float*)d_in[12];
    const float* Woff  = (const float*)d_in[13];
    const float* boff  = (const float*)d_in[14];
    const float* Wout  = (const float*)d_in[15];
    const float* bout  = (const float*)d_in[16];

    bf16 *qlnh,*qlnl,*nh,*nl,*aoh,*aol;
    bf16 *wqTh,*wqTl,*wkvTh,*wkvTl,*wouth,*woutl;
    float *qb,*kvb,*biasq,*biaskv;
    cudaGetSymbolAddress((void**)&qlnh, g_qlnh);
    cudaGetSymbolAddress((void**)&qlnl, g_qlnl);
    cudaGetSymbolAddress((void**)&qb,   g_q);
    cudaGetSymbolAddress((void**)&nh,   g_nh);
    cudaGetSymbolAddress((void**)&nl,   g_nl);
    cudaGetSymbolAddress((void**)&kvb,  g_kv);
    cudaGetSymbolAddress((void**)&aoh,  g_aoh);
    cudaGetSymbolAddress((void**)&aol,  g_aol);
    cudaGetSymbolAddress((void**)&wqTh, g_wqTh);
    cudaGetSymbolAddress((void**)&wqTl, g_wqTl);
    cudaGetSymbolAddress((void**)&wkvTh, g_wkvTh);
    cudaGetSymbolAddress((void**)&wkvTl, g_wkvTl);
    cudaGetSymbolAddress((void**)&wouth, g_wouth);
    cudaGetSymbolAddress((void**)&woutl, g_woutl);
    cudaGetSymbolAddress((void**)&biasq,  g_biasq);
    cudaGetSymbolAddress((void**)&biaskv, g_biaskv);

    cudaFuncSetAttribute(bf16x3_gemm<1>, cudaFuncAttributeMaxDynamicSharedMemorySize, GEMM_SMEM);

    float* out_main = (float*)d_out;
    float* out_off  = out_main + (size_t)MQ * DIMc;

    // 0: all weight prep in one launch
    prep_kernel<<<1216, dim3(32,8)>>>(Wq, lnqg, lnqb, Wk, lnkg, lnkb, bk,
                                      Wv, lnvg, lnvb, bv, Wout,
                                      wqTh, wqTl, wkvTh, wkvTl, wouth, woutl,
                                      biasq, biaskv);
    // 1,2: layernorms
    lnq_kernel <<<MQ, 256>>>(x, px, qlnh, qlnl);
    lnkv_kernel<<<MKV, 256>>>(x, px, nh, nl);

    // 3: kv = nrm @ [foldedWk | foldedWv] + biaskv  (profiled launch)
    bf16x3_gemm<1><<<dim3(2*INNERc/128, MKV/128), 256, GEMM_SMEM>>>(nh, nl, wkvTh, wkvTl, biaskv, kvb, 2*INNERc, DIMc);
    // 4: q = nrm_q @ foldedWq + biasq
    bf16x3_gemm<1><<<dim3(INNERc/128, MQ/128),  256, GEMM_SMEM>>>(qlnh, qlnl, wqTh, wqTl, biasq, qb, INNERc, INNERc);

    // 5,6: offsets + attention
    off_kernel<<<MQ/128, 128>>>(qb, Woff, boff, out_off);
    attn_kernel<<<(MQ*Hh)/8, 256>>>(qb, kvb, out_off, aoh, aol);

    // 7: out = ao @ Wout^T + bout
    bf16x3_gemm<1><<<dim3(DIMc/128, MQ/128), 256, GEMM_SMEM>>>(aoh, aol, wouth, woutl, bout, out_main, DIMc, INNERc);
}